// round 13
// baseline (speedup 1.0000x reference)
#include <cuda_runtime.h>
#include <cuda_fp16.h>
#include <math.h>
#include <stdint.h>

#define Bsz   512
#define IN_   512
#define Hdim  1024
#define HEADS 16
#define DK    64
#define Wwin  32
#define Pdim  64
#define H4    4096
#define KQ    1536
#define KPRE  2560
#define NKV   2048
#define EPSF  1e-5f

// ---------------- device scratch --------------------------------------------
__device__ __half g_xh2h[Bsz * KPRE];                   // [x | ph] fp16
__device__ __half g_qh  [Bsz * Hdim];
__device__ float  g_Q   [Bsz * Hdim];
__device__ float  g_pekv[Wwin * NKV];                   // f32 pe bias rows [w][2048]
__device__ __half g_KV  [(size_t)Wwin * Bsz * NKV];     // [W,B,{K|V}]
__device__ __half g_ctxh[Bsz * Hdim];
__device__ __half g_attnh[Bsz * Hdim];
__device__ float  g_pre [Bsz * H4];
__device__ __half g_pch [(size_t)Wwin * Bsz * Hdim];    // fp16 past_cells
__device__ __half g_Wqh [Hdim * KQ];
__device__ __half g_Wqah[Hdim * Hdim];
__device__ __half g_Wkvh[(size_t)NKV * Hdim];           // [Wk ; Wv] (:, :H)
__device__ __half g_Woh [Hdim * Hdim];
__device__ __half g_Wpreh[(size_t)H4 * KPRE];           // [W_ih | W_hh | W_ac]

// ---------------- helpers ----------------------------------------------------
__device__ __forceinline__ uint32_t smem_u32(const void* p) {
    uint32_t a;
    asm("{ .reg .u64 t; cvta.to.shared.u64 t, %1; cvt.u32.u64 %0, t; }" : "=r"(a) : "l"(p));
    return a;
}
__device__ __forceinline__ float eluf(float x) { return x > 0.f ? x : expm1f(x); }

__device__ __forceinline__ void cp16(uint32_t s, const void* g) {
    asm volatile("cp.async.cg.shared.global [%0], [%1], 16;" :: "r"(s), "l"(g));
}
__device__ __forceinline__ void cp_commit() { asm volatile("cp.async.commit_group;" ::: "memory"); }
template<int N> __device__ __forceinline__ void cp_wait() {
    asm volatile("cp.async.wait_group %0;" :: "n"(N) : "memory");
}
__device__ __forceinline__ void ldsm_x4(uint32_t& r0, uint32_t& r1, uint32_t& r2, uint32_t& r3, uint32_t a) {
    asm volatile("ldmatrix.sync.aligned.m8n8.x4.shared.b16 {%0,%1,%2,%3}, [%4];"
                 : "=r"(r0), "=r"(r1), "=r"(r2), "=r"(r3) : "r"(a));
}
__device__ __forceinline__ void mma16816(float* d, const uint32_t* a, const uint32_t* b) {
    asm volatile("mma.sync.aligned.m16n8k16.row.col.f32.f16.f16.f32 "
        "{%0,%1,%2,%3}, {%4,%5,%6,%7}, {%8,%9}, {%0,%1,%2,%3};"
        : "+f"(d[0]), "+f"(d[1]), "+f"(d[2]), "+f"(d[3])
        : "r"(a[0]), "r"(a[1]), "r"(a[2]), "r"(a[3]), "r"(b[0]), "r"(b[1]));
}
__device__ __forceinline__ void cvt_store(__half* dst, float4 v) {
    __half2* d = (__half2*)dst;
    d[0] = __floats2half2_rn(v.x, v.y);
    d[1] = __floats2half2_rn(v.z, v.w);
}

// ---------------- epilogue descriptor ---------------------------------------
struct Epi {
    const float* bias;
    const float* bias2;
    const float* pe;       // indexed by (row>>9)*N + c
    int          act;
    const float* bn_g;
    const float* bn_b;
    const float* bn_m;
    const float* bn_v;
    int          accumulate;   // f32 out only: C += acc
};

// ---------------- fp16 tensor GEMM: C[M,N] = A*B^T ---------------------------
// CTA tile (WM*MI*16) x (WN*NW*32) x KB, WM*WN warps, warp tile (MI*16)x(NW*32),
// 3-stage cp.async pipeline. Operands fp16. SROW = KB+8 -> ldmatrix conflict-free.

template<int MI, int WM, int WN, int NW, int KB, int HOUT>
__global__ __launch_bounds__(WM * WN * 32, 2)
void hgemm(const __half* __restrict__ A, const __half* __restrict__ Bw,
           void* __restrict__ Cv,
           int M, int N, int K, int lda, int ldb, int ldc, Epi e)
{
    constexpr int TBM = WM * MI * 16;
    constexpr int TBN = WN * NW * 32;
    constexpr int THREADS = WM * WN * 32;
    constexpr int SROW = KB + 8;              // halves per smem row
    constexpr int STG = (TBM + TBN) * SROW;   // halves per stage
    constexpr int CPR = KB / 8;               // 16B chunks per row
    constexpr int RPP = THREADS / CPR;        // rows per cp.async pass
    constexpr int PA = TBM / RPP;
    constexpr int PB = TBN / RPP;
    constexpr int NKS = KB / 16;              // 16-wide k-steps per tile
    constexpr int NJ = 4 * NW;                // 8-col n fragments per warp
    static_assert(PA >= 1 && PB >= 1, "tile/threads mismatch");

    extern __shared__ __half sm[];
    const uint32_t smb = smem_u32(sm);

    const int tid  = threadIdx.x;
    const int lane = tid & 31;
    const int wid  = tid >> 5;
    const int warpm = wid % WM;
    const int warpn = wid / WM;
    const int bm = blockIdx.y * TBM;
    const int bn = blockIdx.x * TBN;
    const int fr = lane >> 2;
    const int fc = lane & 3;

    const int ar = tid / CPR;
    const int ac = (tid % CPR) * 8;

    const __half* Abase = A + (size_t)(bm + ar) * lda + ac;
    const __half* Bbase = Bw + (size_t)(bn + ar) * ldb + ac;
    const uint32_t dA0 = smb + (uint32_t)(ar * SROW + ac) * 2;
    const uint32_t dB0 = smb + (uint32_t)((TBM + ar) * SROW + ac) * 2;

    const int nT = K / KB;

    auto issue = [&](int s, int t) {
        const uint32_t so = (uint32_t)(s * STG) * 2;
        #pragma unroll
        for (int j = 0; j < PA; j++)
            cp16(dA0 + so + (uint32_t)(j * RPP * SROW) * 2,
                 Abase + (size_t)(j * RPP) * lda + t * KB);
        #pragma unroll
        for (int j = 0; j < PB; j++)
            cp16(dB0 + so + (uint32_t)(j * RPP * SROW) * 2,
                 Bbase + (size_t)(j * RPP) * ldb + t * KB);
    };

    float acc[MI][NJ][4];
    #pragma unroll
    for (int i = 0; i < MI; i++)
        #pragma unroll
        for (int j = 0; j < NJ; j++)
            #pragma unroll
            for (int k = 0; k < 4; k++) acc[i][j][k] = 0.f;

    issue(0, 0); cp_commit();
    issue(1, 1); cp_commit();

    const int a_r = ((lane >> 3) & 1) * 8 + (lane & 7);
    const int a_c = (lane >> 4) * 8;
    const int b_r = (lane >> 4) * 8 + (lane & 7);
    const int b_c = ((lane >> 3) & 1) * 8;

    for (int t = 0; t < nT; t++) {
        cp_wait<1>();
        __syncthreads();
        if (t + 2 < nT) issue((t + 2) % 3, t + 2);
        cp_commit();

        const uint32_t sA = smb + (uint32_t)((t % 3) * STG) * 2;
        const uint32_t sB = sA + (uint32_t)(TBM * SROW) * 2;

        #pragma unroll
        for (int ks = 0; ks < NKS; ks++) {
            uint32_t af[MI][4], bf[NJ][2];
            #pragma unroll
            for (int i = 0; i < MI; i++) {
                int r = warpm * (MI * 16) + i * 16 + a_r;
                int c = ks * 16 + a_c;
                ldsm_x4(af[i][0], af[i][1], af[i][2], af[i][3],
                        sA + (uint32_t)(r * SROW + c) * 2);
            }
            #pragma unroll
            for (int jp = 0; jp < 2 * NW; jp++) {
                int n = warpn * (NW * 32) + jp * 16 + b_r;
                int c = ks * 16 + b_c;
                ldsm_x4(bf[2 * jp][0], bf[2 * jp][1], bf[2 * jp + 1][0], bf[2 * jp + 1][1],
                        sB + (uint32_t)(n * SROW + c) * 2);
            }
            #pragma unroll
            for (int i = 0; i < MI; i++)
                #pragma unroll
                for (int j = 0; j < NJ; j++)
                    mma16816(acc[i][j], af[i], bf[j]);
        }
        __syncthreads();
    }

    // ---- epilogue
    const float* pe_row = e.pe ? (e.pe + (size_t)(bm >> 9) * N) : (const float*)0;
    float* Cf = (float*)Cv;
    __half* Ch = (__half*)Cv;

    #pragma unroll
    for (int i = 0; i < MI; i++) {
        const int r0 = bm + warpm * (MI * 16) + i * 16 + fr;
        #pragma unroll
        for (int j = 0; j < NJ; j++) {
            const int c0 = bn + warpn * (NW * 32) + j * 8 + 2 * fc;
            float v[4];
            #pragma unroll
            for (int k = 0; k < 4; k++) {
                float x = acc[i][j][k];
                const int c = c0 + (k & 1);
                if (e.bias)  x += e.bias[c];
                if (e.bias2) x += e.bias2[c];
                if (pe_row)  x += pe_row[c];
                if (e.act)   x = eluf(x);
                if (e.bn_g)  x = (x - e.bn_m[c]) * e.bn_g[c] * rsqrtf(e.bn_v[c] + EPSF) + e.bn_b[c];
                v[k] = x;
            }
            if (HOUT) {
                *(__half2*)(Ch + (size_t)r0 * ldc + c0)       = __floats2half2_rn(v[0], v[1]);
                *(__half2*)(Ch + (size_t)(r0 + 8) * ldc + c0) = __floats2half2_rn(v[2], v[3]);
            } else {
                float* p0 = Cf + (size_t)r0 * ldc + c0;
                float* p1 = Cf + (size_t)(r0 + 8) * ldc + c0;
                if (e.accumulate) {
                    float2 o0 = *(float2*)p0, o1 = *(float2*)p1;
                    v[0] += o0.x; v[1] += o0.y; v[2] += o1.x; v[3] += o1.y;
                }
                *(float2*)p0 = make_float2(v[0], v[1]);
                *(float2*)p1 = make_float2(v[2], v[3]);
            }
        }
    }
}

// ---------------- fused preconversion kernels --------------------------------
// Half of pcells (w 0..15) in float4 units
#define HALF_PC ((size_t)16 * Bsz * Hdim / 4)

// A-part (main stream): pcells first half + Wkv  — deps of KV half 1
#define A_N1 HALF_PC
#define A_N2 (A_N1 + (size_t)NKV * Hdim / 4)

__global__ void preconvA(const float* __restrict__ pcells,
                         const float* __restrict__ Wk, const float* __restrict__ Wv)
{
    size_t i = (size_t)blockIdx.x * blockDim.x + threadIdx.x;
    if (i < A_N1) {
        cvt_store(g_pch + 4 * i, ((const float4*)pcells)[i]);
    } else if (i < A_N2) {
        size_t j = i - A_N1;
        int n = (int)(j >> 8);
        int c = (int)(j & 255) * 4;
        const float* src = (n < Hdim) ? (Wk + (size_t)n * (Hdim + Pdim) + c)
                                      : (Wv + (size_t)(n - Hdim) * (Hdim + Pdim) + c);
        cvt_store(g_Wkvh + (size_t)n * Hdim + c, *(const float4*)src);
    }
}

// B-part (side stream): pcells second half + xh2
#define B_N1 HALF_PC
#define B_N2 (B_N1 + (size_t)Bsz * KQ / 4)

__global__ void preconvB(const float* __restrict__ pcells,
                         const float* __restrict__ x, const float* __restrict__ ph)
{
    size_t i = (size_t)blockIdx.x * blockDim.x + threadIdx.x;
    if (i < B_N1) {
        size_t j = i + HALF_PC;
        cvt_store(g_pch + 4 * j, ((const float4*)pcells)[j]);
    } else if (i < B_N2) {
        size_t j = i - B_N1;
        int row = (int)(j / 384);
        int c = (int)(j - (size_t)row * 384) * 4;
        float4 v = (c < 512) ? *(const float4*)(x + (size_t)row * 512 + c)
                             : *(const float4*)(ph + (size_t)row * 1024 + (c - 512));
        cvt_store(g_xh2h + (size_t)row * KPRE + c, v);
    }
}

#define P2_N1 ((size_t)Hdim * KQ / 4)
#define P2_N2 (P2_N1 + (size_t)Hdim * Hdim / 4)
#define P2_N3 (P2_N2 + (size_t)Hdim * Hdim / 4)
#define P2_N4 (P2_N3 + (size_t)H4 * KPRE / 4)

__global__ void preconv2(const float* __restrict__ Wq, const float* __restrict__ Wqa,
                         const float* __restrict__ Wo,
                         const float* __restrict__ Wih, const float* __restrict__ Whh,
                         const float* __restrict__ Wac)
{
    size_t i = (size_t)blockIdx.x * blockDim.x + threadIdx.x;
    if (i < P2_N1) {
        cvt_store(g_Wqh + 4 * i, ((const float4*)Wq)[i]);
    } else if (i < P2_N2) {
        size_t j = i - P2_N1;
        cvt_store(g_Wqah + 4 * j, ((const float4*)Wqa)[j]);
    } else if (i < P2_N3) {
        size_t j = i - P2_N2;
        cvt_store(g_Woh + 4 * j, ((const float4*)Wo)[j]);
    } else if (i < P2_N4) {
        size_t j = i - P2_N3;
        int row = (int)(j / 640);
        int c = (int)(j - (size_t)row * 640) * 4;
        const float* src;
        if (c < 512)       src = Wih + (size_t)row * 512 + c;
        else if (c < 1536) src = Whh + (size_t)row * 1024 + (c - 512);
        else               src = Wac + (size_t)row * 1024 + (c - 1536);
        cvt_store(g_Wpreh + (size_t)row * KPRE + c, *(const float4*)src);
    }
}

__global__ void pe_proj_kernel(const float* __restrict__ Wk, const float* __restrict__ bk,
                               const float* __restrict__ Wv, const float* __restrict__ bv)
{
    int w = blockIdx.x;
    int h = blockIdx.y * blockDim.x + threadIdx.x;
    const float* wkr = Wk + (size_t)h * (Hdim + Pdim) + Hdim;
    const float* wvr = Wv + (size_t)h * (Hdim + Pdim) + Hdim;
    float ak = bk[h], av = bv[h];
    const float c0 = logf(10000.0f) / (float)Pdim;
    #pragma unroll
    for (int i = 0; i < Pdim / 2; i++) {
        float div = expf(-(2.0f * i) * c0);
        float ang = (float)w * div;
        float s = sinf(ang), cc = cosf(ang);
        ak += s * wkr[2 * i] + cc * wkr[2 * i + 1];
        av += s * wvr[2 * i] + cc * wvr[2 * i + 1];
    }
    g_pekv[w * NKV + h]        = ak;
    g_pekv[w * NKV + Hdim + h] = av;
}

// ---------------- attention ---------------------------------------------------
__global__ __launch_bounds__(1024)
void attention_kernel()
{
    int b   = blockIdx.x;
    int tid = threadIdx.x;
    int warp = tid >> 5, lane = tid & 31;

    __shared__ float qs[Hdim];
    __shared__ float S [HEADS][Wwin];
    __shared__ float ps[HEADS][Wwin];

    qs[tid] = g_Q[(size_t)b * Hdim + tid];
    __syncthreads();

    {
        const __half* Krow = g_KV + ((size_t)warp * Bsz + b) * NKV;
        float acc[HEADS];
        #pragma unroll
        for (int h = 0; h < HEADS; h++) acc[h] = 0.f;
        #pragma unroll
        for (int j = 0; j < 32; j++) {
            int d = lane + 32 * j;
            acc[j >> 1] = fmaf(__half2float(Krow[d]), qs[d], acc[j >> 1]);
        }
        #pragma unroll
        for (int h = 0; h < HEADS; h++) {
            float v = acc[h];
            #pragma unroll
            for (int off = 16; off; off >>= 1)
                v += __shfl_down_sync(0xffffffffu, v, off);
            if (lane == 0) S[h][warp] = v * 0.125f;
        }
    }
    __syncthreads();

    if (warp < HEADS) {
        float s = S[warp][lane];
        float m = s;
        #pragma unroll
        for (int off = 16; off; off >>= 1)
            m = fmaxf(m, __shfl_xor_sync(0xffffffffu, m, off));
        float ev = expf(s - m);
        float sum = ev;
        #pragma unroll
        for (int off = 16; off; off >>= 1)
            sum += __shfl_xor_sync(0xffffffffu, sum, off);
        ps[warp][lane] = ev / sum;
    }
    __syncthreads();

    int h = tid >> 6;
    const __half* Vb = g_KV + (size_t)b * NKV + Hdim + tid;
    float acc = 0.f;
    #pragma unroll
    for (int w = 0; w < Wwin; w++)
        acc = fmaf(ps[h][w], __half2float(Vb[(size_t)w * Bsz * NKV]), acc);
    g_ctxh[(size_t)b * Hdim + tid] = __float2half_rn(acc);
}

__global__ void final_kernel(const float* __restrict__ pcell,
                             const float* __restrict__ gmm, const float* __restrict__ bb,
                             const float* __restrict__ mm, const float* __restrict__ vv,
                             float* __restrict__ out)
{
    int idx = blockIdx.x * blockDim.x + threadIdx.x;
    int r = idx >> 10, c = idx & 1023;
    const float* p = g_pre + (size_t)r * H4;
    float iv = tanhf(p[c]);
    float f  = 1.f / (1.f + expf(-p[1024 + c]));
    float ig = 1.f / (1.f + expf(-p[2048 + c]));
    float o  = 1.f / (1.f + expf(-p[3072 + c]));
    float cell = iv * ig + pcell[idx] * f;
    float e = eluf(cell);
    out[idx] = (o * e - mm[c]) * gmm[c] * rsqrtf(vv[c] + EPSF) + bb[c];
}

// ---------------- host --------------------------------------------------------
#define SMEM_S(TBM, TBN, KB) ((TBM + TBN) * (KB + 8) * 3 * 2)
#define SMEM_SM  SMEM_S(64, 64, 128)    // 104448
#define SMEM_MD  SMEM_S(64, 128, 64)    // 82944
#define SMEM_KV  SMEM_S(128, 128, 64)   // 110592

extern "C" void kernel_launch(void* const* d_in, const int* in_sizes, int n_in,
                              void* d_out, int out_size)
{
    const float* x      = (const float*)d_in[0];
    const float* ph     = (const float*)d_in[1];
    const float* pc     = (const float*)d_in[2];
    const float* pcells = (const float*)d_in[3];
    const float* W_ih   = (const float*)d_in[4];
    const float* b_ih   = (const float*)d_in[5];
    const float* W_hh   = (const float*)d_in[6];
    const float* W_q    = (const float*)d_in[7];
    const float* b_q    = (const float*)d_in[8];
    const float* W_ac   = (const float*)d_in[9];
    const float* b_ac   = (const float*)d_in[10];
    const float* Wq_a   = (const float*)d_in[11];
    const float* bq_a   = (const float*)d_in[12];
    const float* Wk_a   = (const float*)d_in[13];
    const float* bk_a   = (const float*)d_in[14];
    const float* Wv_a   = (const float*)d_in[15];
    const float* bv_a   = (const float*)d_in[16];
    const float* Wo_a   = (const float*)d_in[17];
    const float* bo_a   = (const float*)d_in[18];
    const float* bnag   = (const float*)d_in[19];
    const float* bnab   = (const float*)d_in[20];
    const float* bnam   = (const float*)d_in[21];
    const float* bnav   = (const float*)d_in[22];
    const float* bnpg   = (const float*)d_in[23];
    const float* bnpb   = (const float*)d_in[24];
    const float* bnpm   = (const float*)d_in[25];
    const float* bnpv   = (const float*)d_in[26];
    float* out = (float*)d_out;

    cudaFuncSetAttribute((const void*)hgemm<1,4,2,1,128,0>, cudaFuncAttributeMaxDynamicSharedMemorySize, SMEM_SM);
    cudaFuncSetAttribute((const void*)hgemm<1,4,2,1,128,1>, cudaFuncAttributeMaxDynamicSharedMemorySize, SMEM_SM);
    cudaFuncSetAttribute((const void*)hgemm<2,2,4,1,64,0>,  cudaFuncAttributeMaxDynamicSharedMemorySize, SMEM_MD);
    cudaFuncSetAttribute((const void*)hgemm<4,2,4,1,64,1>,  cudaFuncAttributeMaxDynamicSharedMemorySize, SMEM_KV);

    __half *pxh2, *pqh, *pKV, *pctxh, *pattnh, *ppch, *pWqh, *pWqah, *pWkvh, *pWoh, *pWpreh;
    float *pQ, *ppekv, *ppre;
    cudaGetSymbolAddress((void**)&pxh2,  g_xh2h);
    cudaGetSymbolAddress((void**)&pqh,   g_qh);
    cudaGetSymbolAddress((void**)&pQ,    g_Q);
    cudaGetSymbolAddress((void**)&ppekv, g_pekv);
    cudaGetSymbolAddress((void**)&pKV,   g_KV);
    cudaGetSymbolAddress((void**)&pctxh, g_ctxh);
    cudaGetSymbolAddress((void**)&pattnh,g_attnh);
    cudaGetSymbolAddress((void**)&ppre,  g_pre);
    cudaGetSymbolAddress((void**)&ppch,  g_pch);
    cudaGetSymbolAddress((void**)&pWqh,  g_Wqh);
    cudaGetSymbolAddress((void**)&pWqah, g_Wqah);
    cudaGetSymbolAddress((void**)&pWkvh, g_Wkvh);
    cudaGetSymbolAddress((void**)&pWoh,  g_Woh);
    cudaGetSymbolAddress((void**)&pWpreh,g_Wpreh);

    cudaStream_t s1;
    cudaEvent_t evF, evB, evQ, evP;
    cudaStreamCreateWithFlags(&s1, cudaStreamNonBlocking);
    cudaEventCreateWithFlags(&evF, cudaEventDisableTiming);
    cudaEventCreateWithFlags(&evB, cudaEventDisableTiming);
    cudaEventCreateWithFlags(&evQ, cudaEventDisableTiming);
    cudaEventCreateWithFlags(&evP, cudaEventDisableTiming);

    Epi e0 = {};

    // fork side stream at capture start
    cudaEventRecord(evF, 0);
    cudaStreamWaitEvent(s1, evF, 0);

    // ---- side stream: second-half conversion + q-chain + pre1
    { int nb = (int)((B_N2 + 255) / 256);
      preconvB<<<nb, 256, 0, s1>>>(pcells, x, ph); }
    cudaEventRecord(evB, s1);

    { int nb = (int)((P2_N4 + 255) / 256);
      preconv2<<<nb, 256, 0, s1>>>(W_q, Wq_a, Wo_a, W_ih, W_hh, W_ac); }

    // q = elu(xh @ W_q^T + b_q)  -> fp16
    { Epi e = e0; e.bias = b_q; e.act = 1;
      hgemm<1,4,2,1,128,1><<<dim3(Hdim/64, Bsz/64), 256, SMEM_SM, s1>>>(
          pxh2, pWqh, pqh, Bsz, Hdim, KQ, KPRE, KQ, Hdim, e); }

    // Q = q @ Wq_a^T + bq_a  -> f32
    { Epi e = e0; e.bias = bq_a;
      hgemm<1,4,2,1,128,0><<<dim3(Hdim/64, Bsz/64), 256, SMEM_SM, s1>>>(
          pqh, pWqah, pQ, Bsz, Hdim, Hdim, Hdim, Hdim, Hdim, e); }
    cudaEventRecord(evQ, s1);

    // pre1 = [x|ph] @ W[:, :1536]^T + b_ih + b_ac  -> f32 (hidden under KV)
    { Epi e = e0; e.bias = b_ih; e.bias2 = b_ac;
      hgemm<2,2,4,1,64,0><<<dim3(H4/128, Bsz/64), 256, SMEM_MD, s1>>>(
          pxh2, pWpreh, ppre, Bsz, H4, KQ, KPRE, KPRE, H4, e); }
    cudaEventRecord(evP, s1);

    // ---- main stream: pe bias, first-half conversion, KV half 1
    pe_proj_kernel<<<dim3(Wwin, Hdim / 128), 128>>>(Wk_a, bk_a, Wv_a, bv_a);
    { int nb = (int)((A_N2 + 255) / 256);
      preconvA<<<nb, 256>>>(pcells, Wk_a, Wv_a); }

    // KV half 1: rows 0..8191 (w 0..15)
    { Epi e = e0; e.pe = ppekv; e.act = 1;
      hgemm<4,2,4,1,64,1><<<dim3(NKV/128, 64), 256, SMEM_KV>>>(
          ppch, pWkvh, pKV, Wwin*Bsz/2, NKV, Hdim, Hdim, Hdim, NKV, e); }

    // KV half 2: rows 8192..16383 (w 16..31), needs preconvB
    cudaStreamWaitEvent(0, evB, 0);
    { Epi e = e0; e.pe = ppekv + (size_t)16 * NKV; e.act = 1;
      hgemm<4,2,4,1,64,1><<<dim3(NKV/128, 64), 256, SMEM_KV>>>(
          ppch + (size_t)8192 * Hdim, pWkvh, pKV + (size_t)8192 * NKV,
          Wwin*Bsz/2, NKV, Hdim, Hdim, Hdim, NKV, e); }

    // join: attention needs Q (side) + KV (main)
    cudaStreamWaitEvent(0, evQ, 0);
    attention_kernel<<<Bsz, 1024>>>();

    // attn = BN(elu(ctx @ Wo_a^T + bo_a)) -> fp16
    { Epi e = e0; e.bias = bo_a; e.act = 1;
      e.bn_g = bnag; e.bn_b = bnab; e.bn_m = bnam; e.bn_v = bnav;
      hgemm<1,4,2,1,128,1><<<dim3(Hdim/64, Bsz/64), 256, SMEM_SM>>>(
          pctxh, pWoh, pattnh, Bsz, Hdim, Hdim, Hdim, Hdim, Hdim, e); }

    // pre2: pre += attn @ W_ac^T  (fast 64x64 shape; wait for pre1)
    cudaStreamWaitEvent(0, evP, 0);
    { Epi e = e0; e.accumulate = 1;
      hgemm<1,4,2,1,128,0><<<dim3(H4/64, Bsz/64), 256, SMEM_SM>>>(
          pattnh, pWpreh + KQ, ppre, Bsz, H4, Hdim, Hdim, KPRE, H4, e); }

    // LSTM tail + post-BN -> out
    final_kernel<<<(Bsz * Hdim) / 256, 256>>>(pc, bnpg, bnpb, bnpm, bnpv, out);
}

// round 14
// speedup vs baseline: 1.0427x; 1.0427x over previous
#include <cuda_runtime.h>
#include <cuda_fp16.h>
#include <math.h>
#include <stdint.h>

#define Bsz   512
#define IN_   512
#define Hdim  1024
#define HEADS 16
#define DK    64
#define Wwin  32
#define Pdim  64
#define H4    4096
#define KQ    1536
#define KPRE  2560
#define NKV   2048
#define EPSF  1e-5f

// ---------------- device scratch --------------------------------------------
__device__ __half g_xh2h[Bsz * KPRE];                   // [x | ph] fp16
__device__ __half g_qh  [Bsz * Hdim];
__device__ float  g_Q   [Bsz * Hdim];
__device__ float  g_pekv[Wwin * NKV];                   // f32 pe bias rows [w][2048]
__device__ __half g_KV  [(size_t)Wwin * Bsz * NKV];     // [W,B,{K|V}]
__device__ __half g_ctxh[Bsz * Hdim];
__device__ __half g_attnh[Bsz * Hdim];
__device__ float  g_pre [Bsz * H4];
__device__ __half g_pch [(size_t)Wwin * Bsz * Hdim];    // fp16 past_cells
__device__ __half g_Wqh [Hdim * KQ];
__device__ __half g_Wqah[Hdim * Hdim];
__device__ __half g_Wkvh[(size_t)NKV * Hdim];           // [Wk ; Wv] (:, :H)
__device__ __half g_Woh [Hdim * Hdim];
__device__ __half g_Wpreh[(size_t)H4 * KPRE];           // [W_ih | W_hh | W_ac]

// ---------------- helpers ----------------------------------------------------
__device__ __forceinline__ uint32_t smem_u32(const void* p) {
    uint32_t a;
    asm("{ .reg .u64 t; cvta.to.shared.u64 t, %1; cvt.u32.u64 %0, t; }" : "=r"(a) : "l"(p));
    return a;
}
__device__ __forceinline__ float eluf(float x) { return x > 0.f ? x : expm1f(x); }

__device__ __forceinline__ void cp16(uint32_t s, const void* g) {
    asm volatile("cp.async.cg.shared.global [%0], [%1], 16;" :: "r"(s), "l"(g));
}
__device__ __forceinline__ void cp_commit() { asm volatile("cp.async.commit_group;" ::: "memory"); }
template<int N> __device__ __forceinline__ void cp_wait() {
    asm volatile("cp.async.wait_group %0;" :: "n"(N) : "memory");
}
__device__ __forceinline__ void ldsm_x4(uint32_t& r0, uint32_t& r1, uint32_t& r2, uint32_t& r3, uint32_t a) {
    asm volatile("ldmatrix.sync.aligned.m8n8.x4.shared.b16 {%0,%1,%2,%3}, [%4];"
                 : "=r"(r0), "=r"(r1), "=r"(r2), "=r"(r3) : "r"(a));
}
__device__ __forceinline__ void mma16816(float* d, const uint32_t* a, const uint32_t* b) {
    asm volatile("mma.sync.aligned.m16n8k16.row.col.f32.f16.f16.f32 "
        "{%0,%1,%2,%3}, {%4,%5,%6,%7}, {%8,%9}, {%0,%1,%2,%3};"
        : "+f"(d[0]), "+f"(d[1]), "+f"(d[2]), "+f"(d[3])
        : "r"(a[0]), "r"(a[1]), "r"(a[2]), "r"(a[3]), "r"(b[0]), "r"(b[1]));
}
__device__ __forceinline__ void cvt_store(__half* dst, float4 v) {
    __half2* d = (__half2*)dst;
    d[0] = __floats2half2_rn(v.x, v.y);
    d[1] = __floats2half2_rn(v.z, v.w);
}

// ---------------- epilogue descriptor ---------------------------------------
struct Epi {
    const float* bias;
    const float* bias2;
    const float* pe;       // indexed by (row>>9)*N + c
    int          act;
    const float* bn_g;
    const float* bn_b;
    const float* bn_m;
    const float* bn_v;
    int          accumulate;   // f32 out only: C += acc
};

// ---------------- fp16 tensor GEMM: C[M,N] = A*B^T ---------------------------
// CTA tile (WM*MI*16) x (WN*NW*32) x KB, WM*WN warps, warp tile (MI*16)x(NW*32),
// 3-stage cp.async pipeline. Operands fp16. SROW = KB+8 -> ldmatrix conflict-free.

template<int MI, int WM, int WN, int NW, int KB, int HOUT>
__global__ __launch_bounds__(WM * WN * 32, 2)
void hgemm(const __half* __restrict__ A, const __half* __restrict__ Bw,
           void* __restrict__ Cv,
           int M, int N, int K, int lda, int ldb, int ldc, Epi e)
{
    constexpr int TBM = WM * MI * 16;
    constexpr int TBN = WN * NW * 32;
    constexpr int THREADS = WM * WN * 32;
    constexpr int SROW = KB + 8;              // halves per smem row
    constexpr int STG = (TBM + TBN) * SROW;   // halves per stage
    constexpr int CPR = KB / 8;               // 16B chunks per row
    constexpr int RPP = THREADS / CPR;        // rows per cp.async pass
    constexpr int PA = TBM / RPP;
    constexpr int PB = TBN / RPP;
    constexpr int NKS = KB / 16;              // 16-wide k-steps per tile
    constexpr int NJ = 4 * NW;                // 8-col n fragments per warp
    static_assert(PA >= 1 && PB >= 1, "tile/threads mismatch");

    extern __shared__ __half sm[];
    const uint32_t smb = smem_u32(sm);

    const int tid  = threadIdx.x;
    const int lane = tid & 31;
    const int wid  = tid >> 5;
    const int warpm = wid % WM;
    const int warpn = wid / WM;
    const int bm = blockIdx.y * TBM;
    const int bn = blockIdx.x * TBN;
    const int fr = lane >> 2;
    const int fc = lane & 3;

    const int ar = tid / CPR;
    const int ac = (tid % CPR) * 8;

    const __half* Abase = A + (size_t)(bm + ar) * lda + ac;
    const __half* Bbase = Bw + (size_t)(bn + ar) * ldb + ac;
    const uint32_t dA0 = smb + (uint32_t)(ar * SROW + ac) * 2;
    const uint32_t dB0 = smb + (uint32_t)((TBM + ar) * SROW + ac) * 2;

    const int nT = K / KB;

    auto issue = [&](int s, int t) {
        const uint32_t so = (uint32_t)(s * STG) * 2;
        #pragma unroll
        for (int j = 0; j < PA; j++)
            cp16(dA0 + so + (uint32_t)(j * RPP * SROW) * 2,
                 Abase + (size_t)(j * RPP) * lda + t * KB);
        #pragma unroll
        for (int j = 0; j < PB; j++)
            cp16(dB0 + so + (uint32_t)(j * RPP * SROW) * 2,
                 Bbase + (size_t)(j * RPP) * ldb + t * KB);
    };

    float acc[MI][NJ][4];
    #pragma unroll
    for (int i = 0; i < MI; i++)
        #pragma unroll
        for (int j = 0; j < NJ; j++)
            #pragma unroll
            for (int k = 0; k < 4; k++) acc[i][j][k] = 0.f;

    issue(0, 0); cp_commit();
    issue(1, 1); cp_commit();

    const int a_r = ((lane >> 3) & 1) * 8 + (lane & 7);
    const int a_c = (lane >> 4) * 8;
    const int b_r = (lane >> 4) * 8 + (lane & 7);
    const int b_c = ((lane >> 3) & 1) * 8;

    for (int t = 0; t < nT; t++) {
        cp_wait<1>();
        __syncthreads();
        if (t + 2 < nT) issue((t + 2) % 3, t + 2);
        cp_commit();

        const uint32_t sA = smb + (uint32_t)((t % 3) * STG) * 2;
        const uint32_t sB = sA + (uint32_t)(TBM * SROW) * 2;

        #pragma unroll
        for (int ks = 0; ks < NKS; ks++) {
            uint32_t af[MI][4], bf[NJ][2];
            #pragma unroll
            for (int i = 0; i < MI; i++) {
                int r = warpm * (MI * 16) + i * 16 + a_r;
                int c = ks * 16 + a_c;
                ldsm_x4(af[i][0], af[i][1], af[i][2], af[i][3],
                        sA + (uint32_t)(r * SROW + c) * 2);
            }
            #pragma unroll
            for (int jp = 0; jp < 2 * NW; jp++) {
                int n = warpn * (NW * 32) + jp * 16 + b_r;
                int c = ks * 16 + b_c;
                ldsm_x4(bf[2 * jp][0], bf[2 * jp][1], bf[2 * jp + 1][0], bf[2 * jp + 1][1],
                        sB + (uint32_t)(n * SROW + c) * 2);
            }
            #pragma unroll
            for (int i = 0; i < MI; i++)
                #pragma unroll
                for (int j = 0; j < NJ; j++)
                    mma16816(acc[i][j], af[i], bf[j]);
        }
        __syncthreads();
    }

    // ---- epilogue
    const float* pe_row = e.pe ? (e.pe + (size_t)(bm >> 9) * N) : (const float*)0;
    float* Cf = (float*)Cv;
    __half* Ch = (__half*)Cv;

    #pragma unroll
    for (int i = 0; i < MI; i++) {
        const int r0 = bm + warpm * (MI * 16) + i * 16 + fr;
        #pragma unroll
        for (int j = 0; j < NJ; j++) {
            const int c0 = bn + warpn * (NW * 32) + j * 8 + 2 * fc;
            float v[4];
            #pragma unroll
            for (int k = 0; k < 4; k++) {
                float x = acc[i][j][k];
                const int c = c0 + (k & 1);
                if (e.bias)  x += e.bias[c];
                if (e.bias2) x += e.bias2[c];
                if (pe_row)  x += pe_row[c];
                if (e.act)   x = eluf(x);
                if (e.bn_g)  x = (x - e.bn_m[c]) * e.bn_g[c] * rsqrtf(e.bn_v[c] + EPSF) + e.bn_b[c];
                v[k] = x;
            }
            if (HOUT) {
                *(__half2*)(Ch + (size_t)r0 * ldc + c0)       = __floats2half2_rn(v[0], v[1]);
                *(__half2*)(Ch + (size_t)(r0 + 8) * ldc + c0) = __floats2half2_rn(v[2], v[3]);
            } else {
                float* p0 = Cf + (size_t)r0 * ldc + c0;
                float* p1 = Cf + (size_t)(r0 + 8) * ldc + c0;
                if (e.accumulate) {
                    float2 o0 = *(float2*)p0, o1 = *(float2*)p1;
                    v[0] += o0.x; v[1] += o0.y; v[2] += o1.x; v[3] += o1.y;
                }
                *(float2*)p0 = make_float2(v[0], v[1]);
                *(float2*)p1 = make_float2(v[2], v[3]);
            }
        }
    }
}

// ---------------- fused preconversion kernels --------------------------------
#define P1_N1 ((size_t)Wwin * Bsz * Hdim / 4)
#define P1_N2 (P1_N1 + (size_t)NKV * Hdim / 4)
#define P1_N3 (P1_N2 + (size_t)Bsz * KQ / 4)

__global__ void preconv1(const float* __restrict__ pcells,
                         const float* __restrict__ Wk, const float* __restrict__ Wv,
                         const float* __restrict__ x, const float* __restrict__ ph)
{
    size_t i = (size_t)blockIdx.x * blockDim.x + threadIdx.x;
    if (i < P1_N1) {
        float4 v = ((const float4*)pcells)[i];
        cvt_store(g_pch + 4 * i, v);
    } else if (i < P1_N2) {
        size_t j = i - P1_N1;
        int n = (int)(j >> 8);
        int c = (int)(j & 255) * 4;
        const float* src = (n < Hdim) ? (Wk + (size_t)n * (Hdim + Pdim) + c)
                                      : (Wv + (size_t)(n - Hdim) * (Hdim + Pdim) + c);
        cvt_store(g_Wkvh + (size_t)n * Hdim + c, *(const float4*)src);
    } else if (i < P1_N3) {
        size_t j = i - P1_N2;
        int row = (int)(j / 384);
        int c = (int)(j - (size_t)row * 384) * 4;
        float4 v = (c < 512) ? *(const float4*)(x + (size_t)row * 512 + c)
                             : *(const float4*)(ph + (size_t)row * 1024 + (c - 512));
        cvt_store(g_xh2h + (size_t)row * KPRE + c, v);
    }
}

#define P2_N1 ((size_t)Hdim * KQ / 4)
#define P2_N2 (P2_N1 + (size_t)Hdim * Hdim / 4)
#define P2_N3 (P2_N2 + (size_t)Hdim * Hdim / 4)
#define P2_N4 (P2_N3 + (size_t)H4 * KPRE / 4)

__global__ void preconv2(const float* __restrict__ Wq, const float* __restrict__ Wqa,
                         const float* __restrict__ Wo,
                         const float* __restrict__ Wih, const float* __restrict__ Whh,
                         const float* __restrict__ Wac)
{
    size_t i = (size_t)blockIdx.x * blockDim.x + threadIdx.x;
    if (i < P2_N1) {
        cvt_store(g_Wqh + 4 * i, ((const float4*)Wq)[i]);
    } else if (i < P2_N2) {
        size_t j = i - P2_N1;
        cvt_store(g_Wqah + 4 * j, ((const float4*)Wqa)[j]);
    } else if (i < P2_N3) {
        size_t j = i - P2_N2;
        cvt_store(g_Woh + 4 * j, ((const float4*)Wo)[j]);
    } else if (i < P2_N4) {
        size_t j = i - P2_N3;
        int row = (int)(j / 640);
        int c = (int)(j - (size_t)row * 640) * 4;
        const float* src;
        if (c < 512)       src = Wih + (size_t)row * 512 + c;
        else if (c < 1536) src = Whh + (size_t)row * 1024 + (c - 512);
        else               src = Wac + (size_t)row * 1024 + (c - 1536);
        cvt_store(g_Wpreh + (size_t)row * KPRE + c, *(const float4*)src);
    }
}

__global__ void pe_proj_kernel(const float* __restrict__ Wk, const float* __restrict__ bk,
                               const float* __restrict__ Wv, const float* __restrict__ bv)
{
    int w = blockIdx.x;
    int h = blockIdx.y * blockDim.x + threadIdx.x;
    const float* wkr = Wk + (size_t)h * (Hdim + Pdim) + Hdim;
    const float* wvr = Wv + (size_t)h * (Hdim + Pdim) + Hdim;
    float ak = bk[h], av = bv[h];
    const float c0 = logf(10000.0f) / (float)Pdim;
    #pragma unroll
    for (int i = 0; i < Pdim / 2; i++) {
        float div = expf(-(2.0f * i) * c0);
        float ang = (float)w * div;
        float s = sinf(ang), cc = cosf(ang);
        ak += s * wkr[2 * i] + cc * wkr[2 * i + 1];
        av += s * wvr[2 * i] + cc * wvr[2 * i + 1];
    }
    g_pekv[w * NKV + h]        = ak;
    g_pekv[w * NKV + Hdim + h] = av;
}

// ---------------- attention ---------------------------------------------------
__global__ __launch_bounds__(1024)
void attention_kernel()
{
    int b   = blockIdx.x;
    int tid = threadIdx.x;
    int warp = tid >> 5, lane = tid & 31;

    __shared__ float qs[Hdim];
    __shared__ float S [HEADS][Wwin];
    __shared__ float ps[HEADS][Wwin];

    qs[tid] = g_Q[(size_t)b * Hdim + tid];
    __syncthreads();

    {
        const __half* Krow = g_KV + ((size_t)warp * Bsz + b) * NKV;
        float acc[HEADS];
        #pragma unroll
        for (int h = 0; h < HEADS; h++) acc[h] = 0.f;
        #pragma unroll
        for (int j = 0; j < 32; j++) {
            int d = lane + 32 * j;
            acc[j >> 1] = fmaf(__half2float(Krow[d]), qs[d], acc[j >> 1]);
        }
        #pragma unroll
        for (int h = 0; h < HEADS; h++) {
            float v = acc[h];
            #pragma unroll
            for (int off = 16; off; off >>= 1)
                v += __shfl_down_sync(0xffffffffu, v, off);
            if (lane == 0) S[h][warp] = v * 0.125f;
        }
    }
    __syncthreads();

    if (warp < HEADS) {
        float s = S[warp][lane];
        float m = s;
        #pragma unroll
        for (int off = 16; off; off >>= 1)
            m = fmaxf(m, __shfl_xor_sync(0xffffffffu, m, off));
        float ev = expf(s - m);
        float sum = ev;
        #pragma unroll
        for (int off = 16; off; off >>= 1)
            sum += __shfl_xor_sync(0xffffffffu, sum, off);
        ps[warp][lane] = ev / sum;
    }
    __syncthreads();

    int h = tid >> 6;
    const __half* Vb = g_KV + (size_t)b * NKV + Hdim + tid;
    float acc = 0.f;
    #pragma unroll
    for (int w = 0; w < Wwin; w++)
        acc = fmaf(ps[h][w], __half2float(Vb[(size_t)w * Bsz * NKV]), acc);
    g_ctxh[(size_t)b * Hdim + tid] = __float2half_rn(acc);
}

__global__ void final_kernel(const float* __restrict__ pcell,
                             const float* __restrict__ gmm, const float* __restrict__ bb,
                             const float* __restrict__ mm, const float* __restrict__ vv,
                             float* __restrict__ out)
{
    int idx = blockIdx.x * blockDim.x + threadIdx.x;
    int r = idx >> 10, c = idx & 1023;
    const float* p = g_pre + (size_t)r * H4;
    float iv = tanhf(p[c]);
    float f  = 1.f / (1.f + expf(-p[1024 + c]));
    float ig = 1.f / (1.f + expf(-p[2048 + c]));
    float o  = 1.f / (1.f + expf(-p[3072 + c]));
    float cell = iv * ig + pcell[idx] * f;
    float e = eluf(cell);
    out[idx] = (o * e - mm[c]) * gmm[c] * rsqrtf(vv[c] + EPSF) + bb[c];
}

// ---------------- host --------------------------------------------------------
#define SMEM_S(TBM, TBN, KB) ((TBM + TBN) * (KB + 8) * 3 * 2)
#define SMEM_SM  SMEM_S(64, 64, 128)    // 104448
#define SMEM_MD  SMEM_S(64, 128, 64)    // 82944
#define SMEM_KV  SMEM_S(128, 128, 64)   // 110592

extern "C" void kernel_launch(void* const* d_in, const int* in_sizes, int n_in,
                              void* d_out, int out_size)
{
    const float* x      = (const float*)d_in[0];
    const float* ph     = (const float*)d_in[1];
    const float* pc     = (const float*)d_in[2];
    const float* pcells = (const float*)d_in[3];
    const float* W_ih   = (const float*)d_in[4];
    const float* b_ih   = (const float*)d_in[5];
    const float* W_hh   = (const float*)d_in[6];
    const float* W_q    = (const float*)d_in[7];
    const float* b_q    = (const float*)d_in[8];
    const float* W_ac   = (const float*)d_in[9];
    const float* b_ac   = (const float*)d_in[10];
    const float* Wq_a   = (const float*)d_in[11];
    const float* bq_a   = (const float*)d_in[12];
    const float* Wk_a   = (const float*)d_in[13];
    const float* bk_a   = (const float*)d_in[14];
    const float* Wv_a   = (const float*)d_in[15];
    const float* bv_a   = (const float*)d_in[16];
    const float* Wo_a   = (const float*)d_in[17];
    const float* bo_a   = (const float*)d_in[18];
    const float* bnag   = (const float*)d_in[19];
    const float* bnab   = (const float*)d_in[20];
    const float* bnam   = (const float*)d_in[21];
    const float* bnav   = (const float*)d_in[22];
    const float* bnpg   = (const float*)d_in[23];
    const float* bnpb   = (const float*)d_in[24];
    const float* bnpm   = (const float*)d_in[25];
    const float* bnpv   = (const float*)d_in[26];
    float* out = (float*)d_out;

    cudaFuncSetAttribute((const void*)hgemm<1,4,2,1,128,0>, cudaFuncAttributeMaxDynamicSharedMemorySize, SMEM_SM);
    cudaFuncSetAttribute((const void*)hgemm<1,4,2,1,128,1>, cudaFuncAttributeMaxDynamicSharedMemorySize, SMEM_SM);
    cudaFuncSetAttribute((const void*)hgemm<2,2,4,1,64,0>,  cudaFuncAttributeMaxDynamicSharedMemorySize, SMEM_MD);
    cudaFuncSetAttribute((const void*)hgemm<4,2,4,1,64,1>,  cudaFuncAttributeMaxDynamicSharedMemorySize, SMEM_KV);

    __half *pxh2, *pqh, *pKV, *pctxh, *pattnh, *ppch, *pWqh, *pWqah, *pWkvh, *pWoh, *pWpreh;
    float *pQ, *ppekv, *ppre;
    cudaGetSymbolAddress((void**)&pxh2,  g_xh2h);
    cudaGetSymbolAddress((void**)&pqh,   g_qh);
    cudaGetSymbolAddress((void**)&pQ,    g_Q);
    cudaGetSymbolAddress((void**)&ppekv, g_pekv);
    cudaGetSymbolAddress((void**)&pKV,   g_KV);
    cudaGetSymbolAddress((void**)&pctxh, g_ctxh);
    cudaGetSymbolAddress((void**)&pattnh,g_attnh);
    cudaGetSymbolAddress((void**)&ppre,  g_pre);
    cudaGetSymbolAddress((void**)&ppch,  g_pch);
    cudaGetSymbolAddress((void**)&pWqh,  g_Wqh);
    cudaGetSymbolAddress((void**)&pWqah, g_Wqah);
    cudaGetSymbolAddress((void**)&pWkvh, g_Wkvh);
    cudaGetSymbolAddress((void**)&pWoh,  g_Woh);
    cudaGetSymbolAddress((void**)&pWpreh,g_Wpreh);

    cudaStream_t s1;
    cudaEvent_t evF, evQ, evP;
    cudaStreamCreateWithFlags(&s1, cudaStreamNonBlocking);
    cudaEventCreateWithFlags(&evF, cudaEventDisableTiming);
    cudaEventCreateWithFlags(&evQ, cudaEventDisableTiming);
    cudaEventCreateWithFlags(&evP, cudaEventDisableTiming);

    Epi e0 = {};

    // 0) main: KV-gemm dependencies
    { int nb = (int)((P1_N3 + 255) / 256);
      preconv1<<<nb, 256>>>(pcells, Wk_a, Wv_a, x, ph); }
    // 1)
    pe_proj_kernel<<<dim3(Wwin, Hdim / 128), 128>>>(Wk_a, bk_a, Wv_a, bv_a);

    // fork side branch
    cudaEventRecord(evF, 0);
    cudaStreamWaitEvent(s1, evF, 0);

    // 2)
    { int nb = (int)((P2_N4 + 255) / 256);
      preconv2<<<nb, 256, 0, s1>>>(W_q, Wq_a, Wo_a, W_ih, W_hh, W_ac); }

    // 3) q = elu(xh @ W_q^T + b_q)  -> fp16
    { Epi e = e0; e.bias = b_q; e.act = 1;
      hgemm<1,4,2,1,128,1><<<dim3(Hdim/64, Bsz/64), 256, SMEM_SM, s1>>>(
          pxh2, pWqh, pqh, Bsz, Hdim, KQ, KPRE, KQ, Hdim, e); }

    // 4) Q = q @ Wq_a^T + bq_a  -> f32
    { Epi e = e0; e.bias = bq_a;
      hgemm<1,4,2,1,128,0><<<dim3(Hdim/64, Bsz/64), 256, SMEM_SM, s1>>>(
          pqh, pWqah, pQ, Bsz, Hdim, Hdim, Hdim, Hdim, Hdim, e); }
    cudaEventRecord(evQ, s1);

    // 5) main: dominant KV GEMM — proven R10 config (128x128x64, 8 warps, 2 CTA/SM)
    { Epi e = e0; e.pe = ppekv; e.act = 1;
      hgemm<4,2,4,1,64,1><<<dim3(NKV/128, (Wwin*Bsz)/128), 256, SMEM_KV>>>(
          ppch, pWkvh, pKV, Wwin*Bsz, NKV, Hdim, Hdim, Hdim, NKV, e); }

    // 6) side: pre1 = [x|ph] @ W[:, :1536]^T + b_ih + b_ac  (hidden under KV)
    { Epi e = e0; e.bias = b_ih; e.bias2 = b_ac;
      hgemm<2,2,4,1,64,0><<<dim3(H4/128, Bsz/64), 256, SMEM_MD, s1>>>(
          pxh2, pWpreh, ppre, Bsz, H4, KQ, KPRE, KPRE, H4, e); }
    cudaEventRecord(evP, s1);

    // 7) join: attention needs Q (side) + KV (main)
    cudaStreamWaitEvent(0, evQ, 0);
    attention_kernel<<<Bsz, 1024>>>();

    // 8) attn = BN(elu(ctx @ Wo_a^T + bo_a)) -> fp16
    { Epi e = e0; e.bias = bo_a; e.act = 1;
      e.bn_g = bnag; e.bn_b = bnab; e.bn_m = bnam; e.bn_v = bnav;
      hgemm<1,4,2,1,128,1><<<dim3(Hdim/64, Bsz/64), 256, SMEM_SM>>>(
          pctxh, pWoh, pattnh, Bsz, Hdim, Hdim, Hdim, Hdim, Hdim, e); }

    // 9) pre2: pre += attn @ W_ac^T  (fast 64x64 shape; wait for pre1)
    cudaStreamWaitEvent(0, evP, 0);
    { Epi e = e0; e.accumulate = 1;
      hgemm<1,4,2,1,128,0><<<dim3(H4/64, Bsz/64), 256, SMEM_SM>>>(
          pattnh, pWpreh + KQ, ppre, Bsz, H4, Hdim, Hdim, KPRE, H4, e); }

    // 10) LSTM tail + post-BN -> out
    final_kernel<<<(Bsz * Hdim) / 256, 256>>>(pc, bnpg, bnpb, bnpm, bnpv, out);
}

// round 15
// speedup vs baseline: 1.0478x; 1.0049x over previous
#include <cuda_runtime.h>
#include <cuda_fp16.h>
#include <math.h>
#include <stdint.h>

#define Bsz   512
#define IN_   512
#define Hdim  1024
#define HEADS 16
#define DK    64
#define Wwin  32
#define Pdim  64
#define H4    4096
#define KQ    1536
#define KPRE  2560
#define NKV   2048
#define EPSF  1e-5f

// ---------------- device scratch --------------------------------------------
__device__ __half g_xh2h[Bsz * KPRE];                   // [x | ph] fp16
__device__ __half g_qh  [Bsz * Hdim];
__device__ float  g_Q   [Bsz * Hdim];
__device__ float  g_pekv[Wwin * NKV];                   // f32 pe bias rows [w][2048]
__device__ __half g_KV  [(size_t)Wwin * Bsz * NKV];     // [W,B,{K|V}]
__device__ __half g_ctxh[Bsz * Hdim];
__device__ __half g_attnh[Bsz * Hdim];
__device__ float  g_pre [Bsz * H4];
__device__ __half g_pch [(size_t)Wwin * Bsz * Hdim];    // fp16 past_cells
__device__ __half g_Wqh [Hdim * KQ];
__device__ __half g_Wqah[Hdim * Hdim];
__device__ __half g_Wkvh[(size_t)NKV * Hdim];           // [Wk ; Wv] (:, :H)
__device__ __half g_Woh [Hdim * Hdim];
__device__ __half g_Wpreh[(size_t)H4 * KPRE];           // [W_ih | W_hh | W_ac]

// ---------------- helpers ----------------------------------------------------
__device__ __forceinline__ uint32_t smem_u32(const void* p) {
    uint32_t a;
    asm("{ .reg .u64 t; cvta.to.shared.u64 t, %1; cvt.u32.u64 %0, t; }" : "=r"(a) : "l"(p));
    return a;
}
__device__ __forceinline__ float eluf(float x) { return x > 0.f ? x : expm1f(x); }

__device__ __forceinline__ void cp16(uint32_t s, const void* g) {
    asm volatile("cp.async.cg.shared.global [%0], [%1], 16;" :: "r"(s), "l"(g));
}
__device__ __forceinline__ void cp_commit() { asm volatile("cp.async.commit_group;" ::: "memory"); }
template<int N> __device__ __forceinline__ void cp_wait() {
    asm volatile("cp.async.wait_group %0;" :: "n"(N) : "memory");
}
__device__ __forceinline__ void ldsm_x4(uint32_t& r0, uint32_t& r1, uint32_t& r2, uint32_t& r3, uint32_t a) {
    asm volatile("ldmatrix.sync.aligned.m8n8.x4.shared.b16 {%0,%1,%2,%3}, [%4];"
                 : "=r"(r0), "=r"(r1), "=r"(r2), "=r"(r3) : "r"(a));
}
__device__ __forceinline__ void mma16816(float* d, const uint32_t* a, const uint32_t* b) {
    asm volatile("mma.sync.aligned.m16n8k16.row.col.f32.f16.f16.f32 "
        "{%0,%1,%2,%3}, {%4,%5,%6,%7}, {%8,%9}, {%0,%1,%2,%3};"
        : "+f"(d[0]), "+f"(d[1]), "+f"(d[2]), "+f"(d[3])
        : "r"(a[0]), "r"(a[1]), "r"(a[2]), "r"(a[3]), "r"(b[0]), "r"(b[1]));
}
__device__ __forceinline__ void cvt_store(__half* dst, float4 v) {
    __half2* d = (__half2*)dst;
    d[0] = __floats2half2_rn(v.x, v.y);
    d[1] = __floats2half2_rn(v.z, v.w);
}

// ---------------- epilogue descriptor ---------------------------------------
struct Epi {
    const float* bias;
    const float* bias2;
    const float* pe;       // indexed by (row>>9)*N + c
    int          act;
    const float* bn_g;
    const float* bn_b;
    const float* bn_m;
    const float* bn_v;
    int          accumulate;   // f32 out only: C += acc
};

// ---------------- fp16 tensor GEMM: C[M,N] = A*B^T ---------------------------
// CTA tile (WM*MI*16) x (WN*NW*32) x KB, WM*WN warps, warp tile (MI*16)x(NW*32),
// 3-stage cp.async pipeline. Operands fp16. SROW = KB+8 -> ldmatrix conflict-free.

template<int MI, int WM, int WN, int NW, int KB, int HOUT>
__global__ __launch_bounds__(WM * WN * 32, 2)
void hgemm(const __half* __restrict__ A, const __half* __restrict__ Bw,
           void* __restrict__ Cv,
           int M, int N, int K, int lda, int ldb, int ldc, Epi e)
{
    constexpr int TBM = WM * MI * 16;
    constexpr int TBN = WN * NW * 32;
    constexpr int THREADS = WM * WN * 32;
    constexpr int SROW = KB + 8;              // halves per smem row
    constexpr int STG = (TBM + TBN) * SROW;   // halves per stage
    constexpr int CPR = KB / 8;               // 16B chunks per row
    constexpr int RPP = THREADS / CPR;        // rows per cp.async pass
    constexpr int PA = TBM / RPP;
    constexpr int PB = TBN / RPP;
    constexpr int NKS = KB / 16;              // 16-wide k-steps per tile
    constexpr int NJ = 4 * NW;                // 8-col n fragments per warp
    static_assert(PA >= 1 && PB >= 1, "tile/threads mismatch");

    extern __shared__ __half sm[];
    const uint32_t smb = smem_u32(sm);

    const int tid  = threadIdx.x;
    const int lane = tid & 31;
    const int wid  = tid >> 5;
    const int warpm = wid % WM;
    const int warpn = wid / WM;
    const int bm = blockIdx.y * TBM;
    const int bn = blockIdx.x * TBN;
    const int fr = lane >> 2;
    const int fc = lane & 3;

    const int ar = tid / CPR;
    const int ac = (tid % CPR) * 8;

    const __half* Abase = A + (size_t)(bm + ar) * lda + ac;
    const __half* Bbase = Bw + (size_t)(bn + ar) * ldb + ac;
    const uint32_t dA0 = smb + (uint32_t)(ar * SROW + ac) * 2;
    const uint32_t dB0 = smb + (uint32_t)((TBM + ar) * SROW + ac) * 2;

    const int nT = K / KB;

    auto issue = [&](int s, int t) {
        const uint32_t so = (uint32_t)(s * STG) * 2;
        #pragma unroll
        for (int j = 0; j < PA; j++)
            cp16(dA0 + so + (uint32_t)(j * RPP * SROW) * 2,
                 Abase + (size_t)(j * RPP) * lda + t * KB);
        #pragma unroll
        for (int j = 0; j < PB; j++)
            cp16(dB0 + so + (uint32_t)(j * RPP * SROW) * 2,
                 Bbase + (size_t)(j * RPP) * ldb + t * KB);
    };

    float acc[MI][NJ][4];
    #pragma unroll
    for (int i = 0; i < MI; i++)
        #pragma unroll
        for (int j = 0; j < NJ; j++)
            #pragma unroll
            for (int k = 0; k < 4; k++) acc[i][j][k] = 0.f;

    issue(0, 0); cp_commit();
    issue(1, 1); cp_commit();

    const int a_r = ((lane >> 3) & 1) * 8 + (lane & 7);
    const int a_c = (lane >> 4) * 8;
    const int b_r = (lane >> 4) * 8 + (lane & 7);
    const int b_c = ((lane >> 3) & 1) * 8;

    for (int t = 0; t < nT; t++) {
        cp_wait<1>();
        __syncthreads();
        if (t + 2 < nT) issue((t + 2) % 3, t + 2);
        cp_commit();

        const uint32_t sA = smb + (uint32_t)((t % 3) * STG) * 2;
        const uint32_t sB = sA + (uint32_t)(TBM * SROW) * 2;

        #pragma unroll
        for (int ks = 0; ks < NKS; ks++) {
            uint32_t af[MI][4], bf[NJ][2];
            #pragma unroll
            for (int i = 0; i < MI; i++) {
                int r = warpm * (MI * 16) + i * 16 + a_r;
                int c = ks * 16 + a_c;
                ldsm_x4(af[i][0], af[i][1], af[i][2], af[i][3],
                        sA + (uint32_t)(r * SROW + c) * 2);
            }
            #pragma unroll
            for (int jp = 0; jp < 2 * NW; jp++) {
                int n = warpn * (NW * 32) + jp * 16 + b_r;
                int c = ks * 16 + b_c;
                ldsm_x4(bf[2 * jp][0], bf[2 * jp][1], bf[2 * jp + 1][0], bf[2 * jp + 1][1],
                        sB + (uint32_t)(n * SROW + c) * 2);
            }
            #pragma unroll
            for (int i = 0; i < MI; i++)
                #pragma unroll
                for (int j = 0; j < NJ; j++)
                    mma16816(acc[i][j], af[i], bf[j]);
        }
        __syncthreads();
    }

    // ---- epilogue
    const float* pe_row = e.pe ? (e.pe + (size_t)(bm >> 9) * N) : (const float*)0;
    float* Cf = (float*)Cv;
    __half* Ch = (__half*)Cv;

    #pragma unroll
    for (int i = 0; i < MI; i++) {
        const int r0 = bm + warpm * (MI * 16) + i * 16 + fr;
        #pragma unroll
        for (int j = 0; j < NJ; j++) {
            const int c0 = bn + warpn * (NW * 32) + j * 8 + 2 * fc;
            float v[4];
            #pragma unroll
            for (int k = 0; k < 4; k++) {
                float x = acc[i][j][k];
                const int c = c0 + (k & 1);
                if (e.bias)  x += e.bias[c];
                if (e.bias2) x += e.bias2[c];
                if (pe_row)  x += pe_row[c];
                if (e.act)   x = eluf(x);
                if (e.bn_g)  x = (x - e.bn_m[c]) * e.bn_g[c] * rsqrtf(e.bn_v[c] + EPSF) + e.bn_b[c];
                v[k] = x;
            }
            if (HOUT) {
                *(__half2*)(Ch + (size_t)r0 * ldc + c0)       = __floats2half2_rn(v[0], v[1]);
                *(__half2*)(Ch + (size_t)(r0 + 8) * ldc + c0) = __floats2half2_rn(v[2], v[3]);
            } else {
                float* p0 = Cf + (size_t)r0 * ldc + c0;
                float* p1 = Cf + (size_t)(r0 + 8) * ldc + c0;
                if (e.accumulate) {
                    float2 o0 = *(float2*)p0, o1 = *(float2*)p1;
                    v[0] += o0.x; v[1] += o0.y; v[2] += o1.x; v[3] += o1.y;
                }
                *(float2*)p0 = make_float2(v[0], v[1]);
                *(float2*)p1 = make_float2(v[2], v[3]);
            }
        }
    }
}

// ---------------- fused preconversion kernels --------------------------------
// preconv1 (main stream): only KV-gemm deps = pch + Wkv
#define P1_N1 ((size_t)Wwin * Bsz * Hdim / 4)
#define P1_N2 (P1_N1 + (size_t)NKV * Hdim / 4)

__global__ void preconv1(const float* __restrict__ pcells,
                         const float* __restrict__ Wk, const float* __restrict__ Wv)
{
    size_t i = (size_t)blockIdx.x * blockDim.x + threadIdx.x;
    if (i < P1_N1) {
        float4 v = ((const float4*)pcells)[i];
        cvt_store(g_pch + 4 * i, v);
    } else if (i < P1_N2) {
        size_t j = i - P1_N1;
        int n = (int)(j >> 8);
        int c = (int)(j & 255) * 4;
        const float* src = (n < Hdim) ? (Wk + (size_t)n * (Hdim + Pdim) + c)
                                      : (Wv + (size_t)(n - Hdim) * (Hdim + Pdim) + c);
        cvt_store(g_Wkvh + (size_t)n * Hdim + c, *(const float4*)src);
    }
}

// preconv2 (side stream): xh2, Wq, Wqa, Wo, Wpre
#define P2_N0 ((size_t)Bsz * KQ / 4)
#define P2_N1 (P2_N0 + (size_t)Hdim * KQ / 4)
#define P2_N2 (P2_N1 + (size_t)Hdim * Hdim / 4)
#define P2_N3 (P2_N2 + (size_t)Hdim * Hdim / 4)
#define P2_N4 (P2_N3 + (size_t)H4 * KPRE / 4)

__global__ void preconv2(const float* __restrict__ x, const float* __restrict__ ph,
                         const float* __restrict__ Wq, const float* __restrict__ Wqa,
                         const float* __restrict__ Wo,
                         const float* __restrict__ Wih, const float* __restrict__ Whh,
                         const float* __restrict__ Wac)
{
    size_t i = (size_t)blockIdx.x * blockDim.x + threadIdx.x;
    if (i < P2_N0) {
        int row = (int)(i / 384);
        int c = (int)(i - (size_t)row * 384) * 4;
        float4 v = (c < 512) ? *(const float4*)(x + (size_t)row * 512 + c)
                             : *(const float4*)(ph + (size_t)row * 1024 + (c - 512));
        cvt_store(g_xh2h + (size_t)row * KPRE + c, v);
    } else if (i < P2_N1) {
        size_t j = i - P2_N0;
        cvt_store(g_Wqh + 4 * j, ((const float4*)Wq)[j]);
    } else if (i < P2_N2) {
        size_t j = i - P2_N1;
        cvt_store(g_Wqah + 4 * j, ((const float4*)Wqa)[j]);
    } else if (i < P2_N3) {
        size_t j = i - P2_N2;
        cvt_store(g_Woh + 4 * j, ((const float4*)Wo)[j]);
    } else if (i < P2_N4) {
        size_t j = i - P2_N3;
        int row = (int)(j / 640);
        int c = (int)(j - (size_t)row * 640) * 4;
        const float* src;
        if (c < 512)       src = Wih + (size_t)row * 512 + c;
        else if (c < 1536) src = Whh + (size_t)row * 1024 + (c - 512);
        else               src = Wac + (size_t)row * 1024 + (c - 1536);
        cvt_store(g_Wpreh + (size_t)row * KPRE + c, *(const float4*)src);
    }
}

__global__ void pe_proj_kernel(const float* __restrict__ Wk, const float* __restrict__ bk,
                               const float* __restrict__ Wv, const float* __restrict__ bv)
{
    int w = blockIdx.x;
    int h = blockIdx.y * blockDim.x + threadIdx.x;
    const float* wkr = Wk + (size_t)h * (Hdim + Pdim) + Hdim;
    const float* wvr = Wv + (size_t)h * (Hdim + Pdim) + Hdim;
    float ak = bk[h], av = bv[h];
    const float c0 = logf(10000.0f) / (float)Pdim;
    #pragma unroll
    for (int i = 0; i < Pdim / 2; i++) {
        float div = expf(-(2.0f * i) * c0);
        float ang = (float)w * div;
        float s = sinf(ang), cc = cosf(ang);
        ak += s * wkr[2 * i] + cc * wkr[2 * i + 1];
        av += s * wvr[2 * i] + cc * wvr[2 * i + 1];
    }
    g_pekv[w * NKV + h]        = ak;
    g_pekv[w * NKV + Hdim + h] = av;
}

// ---------------- attention (vectorized loads) --------------------------------
__global__ __launch_bounds__(1024)
void attention_kernel()
{
    int b   = blockIdx.x;
    int tid = threadIdx.x;
    int warp = tid >> 5, lane = tid & 31;

    __shared__ float qs[Hdim];
    __shared__ float S [HEADS][Wwin];
    __shared__ float ps[HEADS][Wwin];

    qs[tid] = g_Q[(size_t)b * Hdim + tid];
    __syncthreads();

    // ---- scores: warp w handles window position w; uint4 (8-half) chunks.
    // chunk offset o = lane*8 + 256*j  ->  head = lane/8 + 4*j (never straddles).
    {
        const uint4* K4 = (const uint4*)(g_KV + ((size_t)warp * Bsz + b) * NKV);
        const float4* q4 = (const float4*)qs;
        float acc[4];
        #pragma unroll
        for (int j = 0; j < 4; j++) {
            const int o = lane * 8 + 256 * j;
            uint4 kv = K4[o >> 3];
            float4 qa = q4[o >> 2];
            float4 qb = q4[(o >> 2) + 1];
            const __half2* h2 = (const __half2*)&kv;
            float2 k0 = __half22float2(h2[0]);
            float2 k1 = __half22float2(h2[1]);
            float2 k2 = __half22float2(h2[2]);
            float2 k3 = __half22float2(h2[3]);
            float a = k0.x * qa.x + k0.y * qa.y + k1.x * qa.z + k1.y * qa.w;
            a += k2.x * qb.x + k2.y * qb.y + k3.x * qb.z + k3.y * qb.w;
            acc[j] = a;
        }
        #pragma unroll
        for (int j = 0; j < 4; j++) {
            #pragma unroll
            for (int off = 4; off; off >>= 1)
                acc[j] += __shfl_xor_sync(0xffffffffu, acc[j], off);
        }
        if ((lane & 7) == 0) {
            int g = lane >> 3;
            #pragma unroll
            for (int j = 0; j < 4; j++)
                S[g + 4 * j][warp] = acc[j] * 0.125f;   // 1/sqrt(64)
        }
    }
    __syncthreads();

    // ---- softmax: warp h over 32 positions
    if (warp < HEADS) {
        float s = S[warp][lane];
        float m = s;
        #pragma unroll
        for (int off = 16; off; off >>= 1)
            m = fmaxf(m, __shfl_xor_sync(0xffffffffu, m, off));
        float ev = expf(s - m);
        float sum = ev;
        #pragma unroll
        for (int off = 16; off; off >>= 1)
            sum += __shfl_xor_sync(0xffffffffu, sum, off);
        ps[warp][lane] = ev / sum;
    }
    __syncthreads();

    // ---- ctx: threads 0..511, half2 per thread
    if (tid < 512) {
        int h = tid >> 5;                       // head of dims (2t, 2t+1)
        const __half2* Vb2 = (const __half2*)(g_KV + (size_t)b * NKV + Hdim) + tid;
        const size_t stride2 = (size_t)Bsz * NKV / 2;
        float ax = 0.f, ay = 0.f;
        #pragma unroll
        for (int w = 0; w < Wwin; w++) {
            float p = ps[h][w];
            float2 vf = __half22float2(Vb2[(size_t)w * stride2]);
            ax = fmaf(p, vf.x, ax);
            ay = fmaf(p, vf.y, ay);
        }
        ((__half2*)(g_ctxh + (size_t)b * Hdim))[tid] = __floats2half2_rn(ax, ay);
    }
}

__global__ void final_kernel(const float* __restrict__ pcell,
                             const float* __restrict__ gmm, const float* __restrict__ bb,
                             const float* __restrict__ mm, const float* __restrict__ vv,
                             float* __restrict__ out)
{
    int idx = blockIdx.x * blockDim.x + threadIdx.x;
    int r = idx >> 10, c = idx & 1023;
    const float* p = g_pre + (size_t)r * H4;
    float iv = tanhf(p[c]);
    float f  = 1.f / (1.f + expf(-p[1024 + c]));
    float ig = 1.f / (1.f + expf(-p[2048 + c]));
    float o  = 1.f / (1.f + expf(-p[3072 + c]));
    float cell = iv * ig + pcell[idx] * f;
    float e = eluf(cell);
    out[idx] = (o * e - mm[c]) * gmm[c] * rsqrtf(vv[c] + EPSF) + bb[c];
}

// ---------------- host --------------------------------------------------------
#define SMEM_S(TBM, TBN, KB) ((TBM + TBN) * (KB + 8) * 3 * 2)
#define SMEM_SM  SMEM_S(64, 64, 128)    // 104448
#define SMEM_MD  SMEM_S(64, 128, 64)    // 82944
#define SMEM_KV  SMEM_S(128, 128, 64)   // 110592

extern "C" void kernel_launch(void* const* d_in, const int* in_sizes, int n_in,
                              void* d_out, int out_size)
{
    const float* x      = (const float*)d_in[0];
    const float* ph     = (const float*)d_in[1];
    const float* pc     = (const float*)d_in[2];
    const float* pcells = (const float*)d_in[3];
    const float* W_ih   = (const float*)d_in[4];
    const float* b_ih   = (const float*)d_in[5];
    const float* W_hh   = (const float*)d_in[6];
    const float* W_q    = (const float*)d_in[7];
    const float* b_q    = (const float*)d_in[8];
    const float* W_ac   = (const float*)d_in[9];
    const float* b_ac   = (const float*)d_in[10];
    const float* Wq_a   = (const float*)d_in[11];
    const float* bq_a   = (const float*)d_in[12];
    const float* Wk_a   = (const float*)d_in[13];
    const float* bk_a   = (const float*)d_in[14];
    const float* Wv_a   = (const float*)d_in[15];
    const float* bv_a   = (const float*)d_in[16];
    const float* Wo_a   = (const float*)d_in[17];
    const float* bo_a   = (const float*)d_in[18];
    const float* bnag   = (const float*)d_in[19];
    const float* bnab   = (const float*)d_in[20];
    const float* bnam   = (const float*)d_in[21];
    const float* bnav   = (const float*)d_in[22];
    const float* bnpg   = (const float*)d_in[23];
    const float* bnpb   = (const float*)d_in[24];
    const float* bnpm   = (const float*)d_in[25];
    const float* bnpv   = (const float*)d_in[26];
    float* out = (float*)d_out;

    cudaFuncSetAttribute((const void*)hgemm<1,4,2,1,128,0>, cudaFuncAttributeMaxDynamicSharedMemorySize, SMEM_SM);
    cudaFuncSetAttribute((const void*)hgemm<1,4,2,1,128,1>, cudaFuncAttributeMaxDynamicSharedMemorySize, SMEM_SM);
    cudaFuncSetAttribute((const void*)hgemm<2,2,4,1,64,0>,  cudaFuncAttributeMaxDynamicSharedMemorySize, SMEM_MD);
    cudaFuncSetAttribute((const void*)hgemm<4,2,4,1,64,1>,  cudaFuncAttributeMaxDynamicSharedMemorySize, SMEM_KV);

    __half *pxh2, *pqh, *pKV, *pctxh, *pattnh, *ppch, *pWqh, *pWqah, *pWkvh, *pWoh, *pWpreh;
    float *pQ, *ppekv, *ppre;
    cudaGetSymbolAddress((void**)&pxh2,  g_xh2h);
    cudaGetSymbolAddress((void**)&pqh,   g_qh);
    cudaGetSymbolAddress((void**)&pQ,    g_Q);
    cudaGetSymbolAddress((void**)&ppekv, g_pekv);
    cudaGetSymbolAddress((void**)&pKV,   g_KV);
    cudaGetSymbolAddress((void**)&pctxh, g_ctxh);
    cudaGetSymbolAddress((void**)&pattnh,g_attnh);
    cudaGetSymbolAddress((void**)&ppre,  g_pre);
    cudaGetSymbolAddress((void**)&ppch,  g_pch);
    cudaGetSymbolAddress((void**)&pWqh,  g_Wqh);
    cudaGetSymbolAddress((void**)&pWqah, g_Wqah);
    cudaGetSymbolAddress((void**)&pWkvh, g_Wkvh);
    cudaGetSymbolAddress((void**)&pWoh,  g_Woh);
    cudaGetSymbolAddress((void**)&pWpreh,g_Wpreh);

    cudaStream_t s1;
    cudaEvent_t evF, evQ, evP;
    cudaStreamCreateWithFlags(&s1, cudaStreamNonBlocking);
    cudaEventCreateWithFlags(&evF, cudaEventDisableTiming);
    cudaEventCreateWithFlags(&evQ, cudaEventDisableTiming);
    cudaEventCreateWithFlags(&evP, cudaEventDisableTiming);

    Epi e0 = {};

    // fork side stream immediately
    cudaEventRecord(evF, 0);
    cudaStreamWaitEvent(s1, evF, 0);

    // ---- main stream: minimal KV deps, then KV
    { int nb = (int)((P1_N2 + 255) / 256);
      preconv1<<<nb, 256>>>(pcells, Wk_a, Wv_a); }
    pe_proj_kernel<<<dim3(Wwin, Hdim / 128), 128>>>(Wk_a, bk_a, Wv_a, bv_a);

    // ---- side stream: xh2 + weights, then q -> Q, then pre1
    { int nb = (int)((P2_N4 + 255) / 256);
      preconv2<<<nb, 256, 0, s1>>>(x, ph, W_q, Wq_a, Wo_a, W_ih, W_hh, W_ac); }

    { Epi e = e0; e.bias = b_q; e.act = 1;
      hgemm<1,4,2,1,128,1><<<dim3(Hdim/64, Bsz/64), 256, SMEM_SM, s1>>>(
          pxh2, pWqh, pqh, Bsz, Hdim, KQ, KPRE, KQ, Hdim, e); }

    { Epi e = e0; e.bias = bq_a;
      hgemm<1,4,2,1,128,0><<<dim3(Hdim/64, Bsz/64), 256, SMEM_SM, s1>>>(
          pqh, pWqah, pQ, Bsz, Hdim, Hdim, Hdim, Hdim, Hdim, e); }
    cudaEventRecord(evQ, s1);

    // ---- main stream: dominant KV GEMM (proven config, single launch)
    { Epi e = e0; e.pe = ppekv; e.act = 1;
      hgemm<4,2,4,1,64,1><<<dim3(NKV/128, (Wwin*Bsz)/128), 256, SMEM_KV>>>(
          ppch, pWkvh, pKV, Wwin*Bsz, NKV, Hdim, Hdim, Hdim, NKV, e); }

    // side: pre1 = [x|ph] @ W[:, :1536]^T + b_ih + b_ac (hidden under KV)
    { Epi e = e0; e.bias = b_ih; e.bias2 = b_ac;
      hgemm<2,2,4,1,64,0><<<dim3(H4/128, Bsz/64), 256, SMEM_MD, s1>>>(
          pxh2, pWpreh, ppre, Bsz, H4, KQ, KPRE, KPRE, H4, e); }
    cudaEventRecord(evP, s1);

    // join: attention needs Q (side) + KV (main)
    cudaStreamWaitEvent(0, evQ, 0);
    attention_kernel<<<Bsz, 1024>>>();

    // attn = BN(elu(ctx @ Wo_a^T + bo_a)) -> fp16
    { Epi e = e0; e.bias = bo_a; e.act = 1;
      e.bn_g = bnag; e.bn_b = bnab; e.bn_m = bnam; e.bn_v = bnav;
      hgemm<1,4,2,1,128,1><<<dim3(Hdim/64, Bsz/64), 256, SMEM_SM>>>(
          pctxh, pWoh, pattnh, Bsz, Hdim, Hdim, Hdim, Hdim, Hdim, e); }

    // pre2: pre += attn @ W_ac^T  (MD shape: 256 CTAs = sub-one-wave)
    cudaStreamWaitEvent(0, evP, 0);
    { Epi e = e0; e.accumulate = 1;
      hgemm<2,2,4,1,64,0><<<dim3(H4/128, Bsz/64), 256, SMEM_MD>>>(
          pattnh, pWpreh + KQ, ppre, Bsz, H4, Hdim, Hdim, KPRE, H4, e); }

    // LSTM tail + post-BN -> out
    final_kernel<<<(Bsz * Hdim) / 256, 256>>>(pc, bnpg, bnpb, bnpm, bnpv, out);
}

// round 16
// speedup vs baseline: 1.0581x; 1.0098x over previous
#include <cuda_runtime.h>
#include <cuda_fp16.h>
#include <math.h>
#include <stdint.h>

#define Bsz   512
#define IN_   512
#define Hdim  1024
#define HEADS 16
#define DK    64
#define Wwin  32
#define Pdim  64
#define H4    4096
#define KQ    1536
#define KPRE  2560
#define NKV   2048
#define EPSF  1e-5f

// ---------------- device scratch --------------------------------------------
__device__ __half g_xh2h[Bsz * KPRE];                   // [x | ph] fp16
__device__ __half g_qh  [Bsz * Hdim];
__device__ float  g_Q   [Bsz * Hdim];
__device__ float  g_pekv[Wwin * NKV];                   // f32 pe bias rows [w][2048]
__device__ __half g_KV  [(size_t)Wwin * Bsz * NKV];     // [W,B,{K|V}]
__device__ __half g_ctxh[Bsz * Hdim];
__device__ __half g_attnh[Bsz * Hdim];
__device__ float  g_pre [Bsz * H4];
__device__ __half g_pch [(size_t)Wwin * Bsz * Hdim];    // fp16 past_cells
__device__ __half g_Wqh [Hdim * KQ];
__device__ __half g_Wqah[Hdim * Hdim];
__device__ __half g_Wkvh[(size_t)NKV * Hdim];           // [Wk ; Wv] (:, :H)
__device__ __half g_Woh [Hdim * Hdim];
__device__ __half g_Wpreh[(size_t)H4 * KPRE];           // [W_ih | W_hh | W_ac]

// ---------------- helpers ----------------------------------------------------
__device__ __forceinline__ uint32_t smem_u32(const void* p) {
    uint32_t a;
    asm("{ .reg .u64 t; cvta.to.shared.u64 t, %1; cvt.u32.u64 %0, t; }" : "=r"(a) : "l"(p));
    return a;
}
__device__ __forceinline__ float eluf(float x) { return x > 0.f ? x : expm1f(x); }

__device__ __forceinline__ void cp16(uint32_t s, const void* g) {
    asm volatile("cp.async.cg.shared.global [%0], [%1], 16;" :: "r"(s), "l"(g));
}
__device__ __forceinline__ void cp_commit() { asm volatile("cp.async.commit_group;" ::: "memory"); }
template<int N> __device__ __forceinline__ void cp_wait() {
    asm volatile("cp.async.wait_group %0;" :: "n"(N) : "memory");
}
__device__ __forceinline__ void ldsm_x4(uint32_t& r0, uint32_t& r1, uint32_t& r2, uint32_t& r3, uint32_t a) {
    asm volatile("ldmatrix.sync.aligned.m8n8.x4.shared.b16 {%0,%1,%2,%3}, [%4];"
                 : "=r"(r0), "=r"(r1), "=r"(r2), "=r"(r3) : "r"(a));
}
__device__ __forceinline__ void mma16816(float* d, const uint32_t* a, const uint32_t* b) {
    asm volatile("mma.sync.aligned.m16n8k16.row.col.f32.f16.f16.f32 "
        "{%0,%1,%2,%3}, {%4,%5,%6,%7}, {%8,%9}, {%0,%1,%2,%3};"
        : "+f"(d[0]), "+f"(d[1]), "+f"(d[2]), "+f"(d[3])
        : "r"(a[0]), "r"(a[1]), "r"(a[2]), "r"(a[3]), "r"(b[0]), "r"(b[1]));
}
__device__ __forceinline__ void cvt_store(__half* dst, float4 v) {
    __half2* d = (__half2*)dst;
    d[0] = __floats2half2_rn(v.x, v.y);
    d[1] = __floats2half2_rn(v.z, v.w);
}

// ---------------- epilogue descriptor ---------------------------------------
struct Epi {
    const float* bias;
    const float* bias2;
    const float* pe;       // indexed by (row>>9)*N + c
    int          act;
    const float* bn_g;
    const float* bn_b;
    const float* bn_m;
    const float* bn_v;
    int          accumulate;   // f32 out only: C += acc
};

// ---------------- fp16 tensor GEMM: C[M,N] = A*B^T ---------------------------
// CTA tile (WM*MI*16) x (WN*NW*32) x KB, WM*WN warps, warp tile (MI*16)x(NW*32),
// 3-stage cp.async pipeline, ONE barrier per k-tile (issue placed after the
// barrier: stage (t+2)%3's previous readers finished compute(t-1), which every
// warp completed before passing this barrier). Operands fp16. SROW = KB+8.

template<int MI, int WM, int WN, int NW, int KB, int HOUT>
__global__ __launch_bounds__(WM * WN * 32, 2)
void hgemm(const __half* __restrict__ A, const __half* __restrict__ Bw,
           void* __restrict__ Cv,
           int M, int N, int K, int lda, int ldb, int ldc, Epi e)
{
    constexpr int TBM = WM * MI * 16;
    constexpr int TBN = WN * NW * 32;
    constexpr int THREADS = WM * WN * 32;
    constexpr int SROW = KB + 8;              // halves per smem row
    constexpr int STG = (TBM + TBN) * SROW;   // halves per stage
    constexpr int CPR = KB / 8;               // 16B chunks per row
    constexpr int RPP = THREADS / CPR;        // rows per cp.async pass
    constexpr int PA = TBM / RPP;
    constexpr int PB = TBN / RPP;
    constexpr int NKS = KB / 16;              // 16-wide k-steps per tile
    constexpr int NJ = 4 * NW;                // 8-col n fragments per warp
    static_assert(PA >= 1 && PB >= 1, "tile/threads mismatch");

    extern __shared__ __half sm[];
    const uint32_t smb = smem_u32(sm);

    const int tid  = threadIdx.x;
    const int lane = tid & 31;
    const int wid  = tid >> 5;
    const int warpm = wid % WM;
    const int warpn = wid / WM;
    const int bm = blockIdx.y * TBM;
    const int bn = blockIdx.x * TBN;
    const int fr = lane >> 2;
    const int fc = lane & 3;

    const int ar = tid / CPR;
    const int ac = (tid % CPR) * 8;

    const __half* Abase = A + (size_t)(bm + ar) * lda + ac;
    const __half* Bbase = Bw + (size_t)(bn + ar) * ldb + ac;
    const uint32_t dA0 = smb + (uint32_t)(ar * SROW + ac) * 2;
    const uint32_t dB0 = smb + (uint32_t)((TBM + ar) * SROW + ac) * 2;

    const int nT = K / KB;

    auto issue = [&](int s, int t) {
        const uint32_t so = (uint32_t)(s * STG) * 2;
        #pragma unroll
        for (int j = 0; j < PA; j++)
            cp16(dA0 + so + (uint32_t)(j * RPP * SROW) * 2,
                 Abase + (size_t)(j * RPP) * lda + t * KB);
        #pragma unroll
        for (int j = 0; j < PB; j++)
            cp16(dB0 + so + (uint32_t)(j * RPP * SROW) * 2,
                 Bbase + (size_t)(j * RPP) * ldb + t * KB);
    };

    float acc[MI][NJ][4];
    #pragma unroll
    for (int i = 0; i < MI; i++)
        #pragma unroll
        for (int j = 0; j < NJ; j++)
            #pragma unroll
            for (int k = 0; k < 4; k++) acc[i][j][k] = 0.f;

    issue(0, 0); cp_commit();
    issue(1, 1); cp_commit();

    const int a_r = ((lane >> 3) & 1) * 8 + (lane & 7);
    const int a_c = (lane >> 4) * 8;
    const int b_r = (lane >> 4) * 8 + (lane & 7);
    const int b_c = ((lane >> 3) & 1) * 8;

    for (int t = 0; t < nT; t++) {
        cp_wait<1>();
        __syncthreads();
        if (t + 2 < nT) issue((t + 2) % 3, t + 2);
        cp_commit();

        const uint32_t sA = smb + (uint32_t)((t % 3) * STG) * 2;
        const uint32_t sB = sA + (uint32_t)(TBM * SROW) * 2;

        #pragma unroll
        for (int ks = 0; ks < NKS; ks++) {
            uint32_t af[MI][4], bf[NJ][2];
            #pragma unroll
            for (int i = 0; i < MI; i++) {
                int r = warpm * (MI * 16) + i * 16 + a_r;
                int c = ks * 16 + a_c;
                ldsm_x4(af[i][0], af[i][1], af[i][2], af[i][3],
                        sA + (uint32_t)(r * SROW + c) * 2);
            }
            #pragma unroll
            for (int jp = 0; jp < 2 * NW; jp++) {
                int n = warpn * (NW * 32) + jp * 16 + b_r;
                int c = ks * 16 + b_c;
                ldsm_x4(bf[2 * jp][0], bf[2 * jp][1], bf[2 * jp + 1][0], bf[2 * jp + 1][1],
                        sB + (uint32_t)(n * SROW + c) * 2);
            }
            #pragma unroll
            for (int i = 0; i < MI; i++)
                #pragma unroll
                for (int j = 0; j < NJ; j++)
                    mma16816(acc[i][j], af[i], bf[j]);
        }
        // no trailing barrier: top barrier of iteration t+1 provides the
        // write-after-read ordering for stage reuse (see header comment).
    }

    // ---- epilogue
    const float* pe_row = e.pe ? (e.pe + (size_t)(bm >> 9) * N) : (const float*)0;
    float* Cf = (float*)Cv;
    __half* Ch = (__half*)Cv;

    #pragma unroll
    for (int i = 0; i < MI; i++) {
        const int r0 = bm + warpm * (MI * 16) + i * 16 + fr;
        #pragma unroll
        for (int j = 0; j < NJ; j++) {
            const int c0 = bn + warpn * (NW * 32) + j * 8 + 2 * fc;
            float v[4];
            #pragma unroll
            for (int k = 0; k < 4; k++) {
                float x = acc[i][j][k];
                const int c = c0 + (k & 1);
                if (e.bias)  x += e.bias[c];
                if (e.bias2) x += e.bias2[c];
                if (pe_row)  x += pe_row[c];
                if (e.act)   x = eluf(x);
                if (e.bn_g)  x = (x - e.bn_m[c]) * e.bn_g[c] * rsqrtf(e.bn_v[c] + EPSF) + e.bn_b[c];
                v[k] = x;
            }
            if (HOUT) {
                *(__half2*)(Ch + (size_t)r0 * ldc + c0)       = __floats2half2_rn(v[0], v[1]);
                *(__half2*)(Ch + (size_t)(r0 + 8) * ldc + c0) = __floats2half2_rn(v[2], v[3]);
            } else {
                float* p0 = Cf + (size_t)r0 * ldc + c0;
                float* p1 = Cf + (size_t)(r0 + 8) * ldc + c0;
                if (e.accumulate) {
                    float2 o0 = *(float2*)p0, o1 = *(float2*)p1;
                    v[0] += o0.x; v[1] += o0.y; v[2] += o1.x; v[3] += o1.y;
                }
                *(float2*)p0 = make_float2(v[0], v[1]);
                *(float2*)p1 = make_float2(v[2], v[3]);
            }
        }
    }
}

// ---------------- fused preconversion kernels --------------------------------
// preconv1 (main stream): only KV-gemm deps = pch + Wkv
#define P1_N1 ((size_t)Wwin * Bsz * Hdim / 4)
#define P1_N2 (P1_N1 + (size_t)NKV * Hdim / 4)

__global__ void preconv1(const float* __restrict__ pcells,
                         const float* __restrict__ Wk, const float* __restrict__ Wv)
{
    size_t i = (size_t)blockIdx.x * blockDim.x + threadIdx.x;
    if (i < P1_N1) {
        float4 v = ((const float4*)pcells)[i];
        cvt_store(g_pch + 4 * i, v);
    } else if (i < P1_N2) {
        size_t j = i - P1_N1;
        int n = (int)(j >> 8);
        int c = (int)(j & 255) * 4;
        const float* src = (n < Hdim) ? (Wk + (size_t)n * (Hdim + Pdim) + c)
                                      : (Wv + (size_t)(n - Hdim) * (Hdim + Pdim) + c);
        cvt_store(g_Wkvh + (size_t)n * Hdim + c, *(const float4*)src);
    }
}

// preconv2 (side stream): xh2, Wq, Wqa, Wo, Wpre
#define P2_N0 ((size_t)Bsz * KQ / 4)
#define P2_N1 (P2_N0 + (size_t)Hdim * KQ / 4)
#define P2_N2 (P2_N1 + (size_t)Hdim * Hdim / 4)
#define P2_N3 (P2_N2 + (size_t)Hdim * Hdim / 4)
#define P2_N4 (P2_N3 + (size_t)H4 * KPRE / 4)

__global__ void preconv2(const float* __restrict__ x, const float* __restrict__ ph,
                         const float* __restrict__ Wq, const float* __restrict__ Wqa,
                         const float* __restrict__ Wo,
                         const float* __restrict__ Wih, const float* __restrict__ Whh,
                         const float* __restrict__ Wac)
{
    size_t i = (size_t)blockIdx.x * blockDim.x + threadIdx.x;
    if (i < P2_N0) {
        int row = (int)(i / 384);
        int c = (int)(i - (size_t)row * 384) * 4;
        float4 v = (c < 512) ? *(const float4*)(x + (size_t)row * 512 + c)
                             : *(const float4*)(ph + (size_t)row * 1024 + (c - 512));
        cvt_store(g_xh2h + (size_t)row * KPRE + c, v);
    } else if (i < P2_N1) {
        size_t j = i - P2_N0;
        cvt_store(g_Wqh + 4 * j, ((const float4*)Wq)[j]);
    } else if (i < P2_N2) {
        size_t j = i - P2_N1;
        cvt_store(g_Wqah + 4 * j, ((const float4*)Wqa)[j]);
    } else if (i < P2_N3) {
        size_t j = i - P2_N2;
        cvt_store(g_Woh + 4 * j, ((const float4*)Wo)[j]);
    } else if (i < P2_N4) {
        size_t j = i - P2_N3;
        int row = (int)(j / 640);
        int c = (int)(j - (size_t)row * 640) * 4;
        const float* src;
        if (c < 512)       src = Wih + (size_t)row * 512 + c;
        else if (c < 1536) src = Whh + (size_t)row * 1024 + (c - 512);
        else               src = Wac + (size_t)row * 1024 + (c - 1536);
        cvt_store(g_Wpreh + (size_t)row * KPRE + c, *(const float4*)src);
    }
}

__global__ void pe_proj_kernel(const float* __restrict__ Wk, const float* __restrict__ bk,
                               const float* __restrict__ Wv, const float* __restrict__ bv)
{
    int w = blockIdx.x;
    int h = blockIdx.y * blockDim.x + threadIdx.x;
    const float* wkr = Wk + (size_t)h * (Hdim + Pdim) + Hdim;
    const float* wvr = Wv + (size_t)h * (Hdim + Pdim) + Hdim;
    float ak = bk[h], av = bv[h];
    const float c0 = logf(10000.0f) / (float)Pdim;
    #pragma unroll
    for (int i = 0; i < Pdim / 2; i++) {
        float div = expf(-(2.0f * i) * c0);
        float ang = (float)w * div;
        float s = sinf(ang), cc = cosf(ang);
        ak += s * wkr[2 * i] + cc * wkr[2 * i + 1];
        av += s * wvr[2 * i] + cc * wvr[2 * i + 1];
    }
    g_pekv[w * NKV + h]        = ak;
    g_pekv[w * NKV + Hdim + h] = av;
}

// ---------------- attention (vectorized loads) --------------------------------
__global__ __launch_bounds__(1024)
void attention_kernel()
{
    int b   = blockIdx.x;
    int tid = threadIdx.x;
    int warp = tid >> 5, lane = tid & 31;

    __shared__ float qs[Hdim];
    __shared__ float S [HEADS][Wwin];
    __shared__ float ps[HEADS][Wwin];

    qs[tid] = g_Q[(size_t)b * Hdim + tid];
    __syncthreads();

    // ---- scores: warp w handles window position w; uint4 (8-half) chunks.
    {
        const uint4* K4 = (const uint4*)(g_KV + ((size_t)warp * Bsz + b) * NKV);
        const float4* q4 = (const float4*)qs;
        float acc[4];
        #pragma unroll
        for (int j = 0; j < 4; j++) {
            const int o = lane * 8 + 256 * j;
            uint4 kv = K4[o >> 3];
            float4 qa = q4[o >> 2];
            float4 qb = q4[(o >> 2) + 1];
            const __half2* h2 = (const __half2*)&kv;
            float2 k0 = __half22float2(h2[0]);
            float2 k1 = __half22float2(h2[1]);
            float2 k2 = __half22float2(h2[2]);
            float2 k3 = __half22float2(h2[3]);
            float a = k0.x * qa.x + k0.y * qa.y + k1.x * qa.z + k1.y * qa.w;
            a += k2.x * qb.x + k2.y * qb.y + k3.x * qb.z + k3.y * qb.w;
            acc[j] = a;
        }
        #pragma unroll
        for (int j = 0; j < 4; j++) {
            #pragma unroll
            for (int off = 4; off; off >>= 1)
                acc[j] += __shfl_xor_sync(0xffffffffu, acc[j], off);
        }
        if ((lane & 7) == 0) {
            int g = lane >> 3;
            #pragma unroll
            for (int j = 0; j < 4; j++)
                S[g + 4 * j][warp] = acc[j] * 0.125f;   // 1/sqrt(64)
        }
    }
    __syncthreads();

    // ---- softmax: warp h over 32 positions
    if (warp < HEADS) {
        float s = S[warp][lane];
        float m = s;
        #pragma unroll
        for (int off = 16; off; off >>= 1)
            m = fmaxf(m, __shfl_xor_sync(0xffffffffu, m, off));
        float ev = expf(s - m);
        float sum = ev;
        #pragma unroll
        for (int off = 16; off; off >>= 1)
            sum += __shfl_xor_sync(0xffffffffu, sum, off);
        ps[warp][lane] = ev / sum;
    }
    __syncthreads();

    // ---- ctx: threads 0..511, half2 per thread
    if (tid < 512) {
        int h = tid >> 5;
        const __half2* Vb2 = (const __half2*)(g_KV + (size_t)b * NKV + Hdim) + tid;
        const size_t stride2 = (size_t)Bsz * NKV / 2;
        float ax = 0.f, ay = 0.f;
        #pragma unroll
        for (int w = 0; w < Wwin; w++) {
            float p = ps[h][w];
            float2 vf = __half22float2(Vb2[(size_t)w * stride2]);
            ax = fmaf(p, vf.x, ax);
            ay = fmaf(p, vf.y, ay);
        }
        ((__half2*)(g_ctxh + (size_t)b * Hdim))[tid] = __floats2half2_rn(ax, ay);
    }
}

__global__ void final_kernel(const float* __restrict__ pcell,
                             const float* __restrict__ gmm, const float* __restrict__ bb,
                             const float* __restrict__ mm, const float* __restrict__ vv,
                             float* __restrict__ out)
{
    int idx = blockIdx.x * blockDim.x + threadIdx.x;
    int r = idx >> 10, c = idx & 1023;
    const float* p = g_pre + (size_t)r * H4;
    float iv = tanhf(p[c]);
    float f  = 1.f / (1.f + expf(-p[1024 + c]));
    float ig = 1.f / (1.f + expf(-p[2048 + c]));
    float o  = 1.f / (1.f + expf(-p[3072 + c]));
    float cell = iv * ig + pcell[idx] * f;
    float e = eluf(cell);
    out[idx] = (o * e - mm[c]) * gmm[c] * rsqrtf(vv[c] + EPSF) + bb[c];
}

// ---------------- host --------------------------------------------------------
#define SMEM_S(TBM, TBN, KB) ((TBM + TBN) * (KB + 8) * 3 * 2)
#define SMEM_SM  SMEM_S(64, 64, 128)    // 104448
#define SMEM_MD  SMEM_S(64, 128, 64)    // 82944
#define SMEM_KV  SMEM_S(128, 128, 64)   // 110592

extern "C" void kernel_launch(void* const* d_in, const int* in_sizes, int n_in,
                              void* d_out, int out_size)
{
    const float* x      = (const float*)d_in[0];
    const float* ph     = (const float*)d_in[1];
    const float* pc     = (const float*)d_in[2];
    const float* pcells = (const float*)d_in[3];
    const float* W_ih   = (const float*)d_in[4];
    const float* b_ih   = (const float*)d_in[5];
    const float* W_hh   = (const float*)d_in[6];
    const float* W_q    = (const float*)d_in[7];
    const float* b_q    = (const float*)d_in[8];
    const float* W_ac   = (const float*)d_in[9];
    const float* b_ac   = (const float*)d_in[10];
    const float* Wq_a   = (const float*)d_in[11];
    const float* bq_a   = (const float*)d_in[12];
    const float* Wk_a   = (const float*)d_in[13];
    const float* bk_a   = (const float*)d_in[14];
    const float* Wv_a   = (const float*)d_in[15];
    const float* bv_a   = (const float*)d_in[16];
    const float* Wo_a   = (const float*)d_in[17];
    const float* bo_a   = (const float*)d_in[18];
    const float* bnag   = (const float*)d_in[19];
    const float* bnab   = (const float*)d_in[20];
    const float* bnam   = (const float*)d_in[21];
    const float* bnav   = (const float*)d_in[22];
    const float* bnpg   = (const float*)d_in[23];
    const float* bnpb   = (const float*)d_in[24];
    const float* bnpm   = (const float*)d_in[25];
    const float* bnpv   = (const float*)d_in[26];
    float* out = (float*)d_out;

    cudaFuncSetAttribute((const void*)hgemm<1,4,2,1,128,0>, cudaFuncAttributeMaxDynamicSharedMemorySize, SMEM_SM);
    cudaFuncSetAttribute((const void*)hgemm<1,4,2,1,128,1>, cudaFuncAttributeMaxDynamicSharedMemorySize, SMEM_SM);
    cudaFuncSetAttribute((const void*)hgemm<2,2,4,1,64,0>,  cudaFuncAttributeMaxDynamicSharedMemorySize, SMEM_MD);
    cudaFuncSetAttribute((const void*)hgemm<4,2,4,1,64,1>,  cudaFuncAttributeMaxDynamicSharedMemorySize, SMEM_KV);

    __half *pxh2, *pqh, *pKV, *pctxh, *pattnh, *ppch, *pWqh, *pWqah, *pWkvh, *pWoh, *pWpreh;
    float *pQ, *ppekv, *ppre;
    cudaGetSymbolAddress((void**)&pxh2,  g_xh2h);
    cudaGetSymbolAddress((void**)&pqh,   g_qh);
    cudaGetSymbolAddress((void**)&pQ,    g_Q);
    cudaGetSymbolAddress((void**)&ppekv, g_pekv);
    cudaGetSymbolAddress((void**)&pKV,   g_KV);
    cudaGetSymbolAddress((void**)&pctxh, g_ctxh);
    cudaGetSymbolAddress((void**)&pattnh,g_attnh);
    cudaGetSymbolAddress((void**)&ppre,  g_pre);
    cudaGetSymbolAddress((void**)&ppch,  g_pch);
    cudaGetSymbolAddress((void**)&pWqh,  g_Wqh);
    cudaGetSymbolAddress((void**)&pWqah, g_Wqah);
    cudaGetSymbolAddress((void**)&pWkvh, g_Wkvh);
    cudaGetSymbolAddress((void**)&pWoh,  g_Woh);
    cudaGetSymbolAddress((void**)&pWpreh,g_Wpreh);

    cudaStream_t s1;
    cudaEvent_t evF, evQ, evP;
    cudaStreamCreateWithFlags(&s1, cudaStreamNonBlocking);
    cudaEventCreateWithFlags(&evF, cudaEventDisableTiming);
    cudaEventCreateWithFlags(&evQ, cudaEventDisableTiming);
    cudaEventCreateWithFlags(&evP, cudaEventDisableTiming);

    Epi e0 = {};

    // fork side stream immediately
    cudaEventRecord(evF, 0);
    cudaStreamWaitEvent(s1, evF, 0);

    // ---- main stream: minimal KV deps, then KV
    { int nb = (int)((P1_N2 + 255) / 256);
      preconv1<<<nb, 256>>>(pcells, Wk_a, Wv_a); }
    pe_proj_kernel<<<dim3(Wwin, Hdim / 128), 128>>>(Wk_a, bk_a, Wv_a, bv_a);

    // ---- side stream: xh2 + weights, then q -> Q, then pre1
    { int nb = (int)((P2_N4 + 255) / 256);
      preconv2<<<nb, 256, 0, s1>>>(x, ph, W_q, Wq_a, Wo_a, W_ih, W_hh, W_ac); }

    { Epi e = e0; e.bias = b_q; e.act = 1;
      hgemm<1,4,2,1,128,1><<<dim3(Hdim/64, Bsz/64), 256, SMEM_SM, s1>>>(
          pxh2, pWqh, pqh, Bsz, Hdim, KQ, KPRE, KQ, Hdim, e); }

    { Epi e = e0; e.bias = bq_a;
      hgemm<1,4,2,1,128,0><<<dim3(Hdim/64, Bsz/64), 256, SMEM_SM, s1>>>(
          pqh, pWqah, pQ, Bsz, Hdim, Hdim, Hdim, Hdim, Hdim, e); }
    cudaEventRecord(evQ, s1);

    // ---- main stream: dominant KV GEMM (proven config, single launch)
    { Epi e = e0; e.pe = ppekv; e.act = 1;
      hgemm<4,2,4,1,64,1><<<dim3(NKV/128, (Wwin*Bsz)/128), 256, SMEM_KV>>>(
          ppch, pWkvh, pKV, Wwin*Bsz, NKV, Hdim, Hdim, Hdim, NKV, e); }

    // side: pre1 = [x|ph] @ W[:, :1536]^T + b_ih + b_ac (hidden under KV)
    { Epi e = e0; e.bias = b_ih; e.bias2 = b_ac;
      hgemm<2,2,4,1,64,0><<<dim3(H4/128, Bsz/64), 256, SMEM_MD, s1>>>(
          pxh2, pWpreh, ppre, Bsz, H4, KQ, KPRE, KPRE, H4, e); }
    cudaEventRecord(evP, s1);

    // join: attention needs Q (side) + KV (main)
    cudaStreamWaitEvent(0, evQ, 0);
    attention_kernel<<<Bsz, 1024>>>();

    // attn = BN(elu(ctx @ Wo_a^T + bo_a)) -> fp16
    { Epi e = e0; e.bias = bo_a; e.act = 1;
      e.bn_g = bnag; e.bn_b = bnab; e.bn_m = bnam; e.bn_v = bnav;
      hgemm<1,4,2,1,128,1><<<dim3(Hdim/64, Bsz/64), 256, SMEM_SM>>>(
          pctxh, pWoh, pattnh, Bsz, Hdim, Hdim, Hdim, Hdim, Hdim, e); }

    // pre2: pre += attn @ W_ac^T  (MD shape: 256 CTAs = sub-one-wave)
    cudaStreamWaitEvent(0, evP, 0);
    { Epi e = e0; e.accumulate = 1;
      hgemm<2,2,4,1,64,0><<<dim3(H4/128, Bsz/64), 256, SMEM_MD>>>(
          pattnh, pWpreh + KQ, ppre, Bsz, H4, Hdim, Hdim, KPRE, H4, e); }

    // LSTM tail + post-BN -> out
    final_kernel<<<(Bsz * Hdim) / 256, 256>>>(pc, bnpg, bnpb, bnpm, bnpv, out);
}

// round 17
// speedup vs baseline: 1.0980x; 1.0377x over previous
#include <cuda_runtime.h>
#include <cuda_fp16.h>
#include <math.h>
#include <stdint.h>

#define Bsz   512
#define IN_   512
#define Hdim  1024
#define HEADS 16
#define DK    64
#define Wwin  32
#define Pdim  64
#define H4    4096
#define KQ    1536
#define KPRE  2560
#define NKV   2048
#define EPSF  1e-5f

// ---------------- device scratch --------------------------------------------
__device__ __half g_xh2h[Bsz * KPRE];                   // [x | ph] fp16
__device__ __half g_qh  [Bsz * Hdim];
__device__ float  g_Q   [Bsz * Hdim];
__device__ float  g_pekv[Wwin * NKV];                   // f32 pe bias rows [w][2048]
__device__ __half g_KV  [(size_t)Wwin * Bsz * NKV];     // [W,B,{K|V}]
__device__ __half g_ctxh[Bsz * Hdim];
__device__ __half g_attnh[Bsz * Hdim];
__device__ float  g_pre [Bsz * H4];
__device__ __half g_pch [(size_t)Wwin * Bsz * Hdim];    // fp16 past_cells
__device__ __half g_Wqh [Hdim * KQ];
__device__ __half g_Wqah[Hdim * Hdim];
__device__ __half g_Wkvh[(size_t)NKV * Hdim];           // [Wk ; Wv] (:, :H)
__device__ __half g_Woh [Hdim * Hdim];
__device__ __half g_Wpreh[(size_t)H4 * KPRE];           // [W_ih | W_hh | W_ac]

// ---------------- helpers ----------------------------------------------------
__device__ __forceinline__ uint32_t smem_u32(const void* p) {
    uint32_t a;
    asm("{ .reg .u64 t; cvta.to.shared.u64 t, %1; cvt.u32.u64 %0, t; }" : "=r"(a) : "l"(p));
    return a;
}
__device__ __forceinline__ float eluf(float x) { return x > 0.f ? x : expm1f(x); }

__device__ __forceinline__ void cp16(uint32_t s, const void* g) {
    asm volatile("cp.async.cg.shared.global [%0], [%1], 16;" :: "r"(s), "l"(g));
}
__device__ __forceinline__ void cp_commit() { asm volatile("cp.async.commit_group;" ::: "memory"); }
template<int N> __device__ __forceinline__ void cp_wait() {
    asm volatile("cp.async.wait_group %0;" :: "n"(N) : "memory");
}
__device__ __forceinline__ void ldsm_x4(uint32_t& r0, uint32_t& r1, uint32_t& r2, uint32_t& r3, uint32_t a) {
    asm volatile("ldmatrix.sync.aligned.m8n8.x4.shared.b16 {%0,%1,%2,%3}, [%4];"
                 : "=r"(r0), "=r"(r1), "=r"(r2), "=r"(r3) : "r"(a));
}
__device__ __forceinline__ void mma16816(float* d, const uint32_t* a, const uint32_t* b) {
    asm volatile("mma.sync.aligned.m16n8k16.row.col.f32.f16.f16.f32 "
        "{%0,%1,%2,%3}, {%4,%5,%6,%7}, {%8,%9}, {%0,%1,%2,%3};"
        : "+f"(d[0]), "+f"(d[1]), "+f"(d[2]), "+f"(d[3])
        : "r"(a[0]), "r"(a[1]), "r"(a[2]), "r"(a[3]), "r"(b[0]), "r"(b[1]));
}
__device__ __forceinline__ void cvt_store(__half* dst, float4 v) {
    __half2* d = (__half2*)dst;
    d[0] = __floats2half2_rn(v.x, v.y);
    d[1] = __floats2half2_rn(v.z, v.w);
}

// ---------------- epilogue descriptor ---------------------------------------
struct Epi {
    const float* bias;
    const float* bias2;
    const float* pe;       // indexed by (row>>9)*N + c
    int          act;
    const float* bn_g;
    const float* bn_b;
    const float* bn_m;
    const float* bn_v;
    int          accumulate;   // f32 out only: C += acc
};

// ---------------- fp16 tensor GEMM: C[M,N] = A*B^T ---------------------------
// CTA tile (WM*MI*16) x (WN*NW*32) x KB, WM*WN warps, warp tile (MI*16)x(NW*32),
// 3-stage cp.async pipeline, ONE barrier per k-tile (issue placed after the
// barrier: stage (t+2)%3's previous readers finished compute(t-1), which every
// warp completed before passing this barrier). Operands fp16. SROW = KB+8.

template<int MI, int WM, int WN, int NW, int KB, int HOUT>
__global__ __launch_bounds__(WM * WN * 32, 2)
void hgemm(const __half* __restrict__ A, const __half* __restrict__ Bw,
           void* __restrict__ Cv,
           int M, int N, int K, int lda, int ldb, int ldc, Epi e)
{
    constexpr int TBM = WM * MI * 16;
    constexpr int TBN = WN * NW * 32;
    constexpr int THREADS = WM * WN * 32;
    constexpr int SROW = KB + 8;              // halves per smem row
    constexpr int STG = (TBM + TBN) * SROW;   // halves per stage
    constexpr int CPR = KB / 8;               // 16B chunks per row
    constexpr int RPP = THREADS / CPR;        // rows per cp.async pass
    constexpr int PA = TBM / RPP;
    constexpr int PB = TBN / RPP;
    constexpr int NKS = KB / 16;              // 16-wide k-steps per tile
    constexpr int NJ = 4 * NW;                // 8-col n fragments per warp
    static_assert(PA >= 1 && PB >= 1, "tile/threads mismatch");

    extern __shared__ __half sm[];
    const uint32_t smb = smem_u32(sm);

    const int tid  = threadIdx.x;
    const int lane = tid & 31;
    const int wid  = tid >> 5;
    const int warpm = wid % WM;
    const int warpn = wid / WM;
    const int bm = blockIdx.y * TBM;
    const int bn = blockIdx.x * TBN;
    const int fr = lane >> 2;
    const int fc = lane & 3;

    const int ar = tid / CPR;
    const int ac = (tid % CPR) * 8;

    const __half* Abase = A + (size_t)(bm + ar) * lda + ac;
    const __half* Bbase = Bw + (size_t)(bn + ar) * ldb + ac;
    const uint32_t dA0 = smb + (uint32_t)(ar * SROW + ac) * 2;
    const uint32_t dB0 = smb + (uint32_t)((TBM + ar) * SROW + ac) * 2;

    const int nT = K / KB;

    auto issue = [&](int s, int t) {
        const uint32_t so = (uint32_t)(s * STG) * 2;
        #pragma unroll
        for (int j = 0; j < PA; j++)
            cp16(dA0 + so + (uint32_t)(j * RPP * SROW) * 2,
                 Abase + (size_t)(j * RPP) * lda + t * KB);
        #pragma unroll
        for (int j = 0; j < PB; j++)
            cp16(dB0 + so + (uint32_t)(j * RPP * SROW) * 2,
                 Bbase + (size_t)(j * RPP) * ldb + t * KB);
    };

    float acc[MI][NJ][4];
    #pragma unroll
    for (int i = 0; i < MI; i++)
        #pragma unroll
        for (int j = 0; j < NJ; j++)
            #pragma unroll
            for (int k = 0; k < 4; k++) acc[i][j][k] = 0.f;

    issue(0, 0); cp_commit();
    issue(1, 1); cp_commit();

    const int a_r = ((lane >> 3) & 1) * 8 + (lane & 7);
    const int a_c = (lane >> 4) * 8;
    const int b_r = (lane >> 4) * 8 + (lane & 7);
    const int b_c = ((lane >> 3) & 1) * 8;

    for (int t = 0; t < nT; t++) {
        cp_wait<1>();
        __syncthreads();
        if (t + 2 < nT) issue((t + 2) % 3, t + 2);
        cp_commit();

        const uint32_t sA = smb + (uint32_t)((t % 3) * STG) * 2;
        const uint32_t sB = sA + (uint32_t)(TBM * SROW) * 2;

        #pragma unroll
        for (int ks = 0; ks < NKS; ks++) {
            uint32_t af[MI][4], bf[NJ][2];
            #pragma unroll
            for (int i = 0; i < MI; i++) {
                int r = warpm * (MI * 16) + i * 16 + a_r;
                int c = ks * 16 + a_c;
                ldsm_x4(af[i][0], af[i][1], af[i][2], af[i][3],
                        sA + (uint32_t)(r * SROW + c) * 2);
            }
            #pragma unroll
            for (int jp = 0; jp < 2 * NW; jp++) {
                int n = warpn * (NW * 32) + jp * 16 + b_r;
                int c = ks * 16 + b_c;
                ldsm_x4(bf[2 * jp][0], bf[2 * jp][1], bf[2 * jp + 1][0], bf[2 * jp + 1][1],
                        sB + (uint32_t)(n * SROW + c) * 2);
            }
            #pragma unroll
            for (int i = 0; i < MI; i++)
                #pragma unroll
                for (int j = 0; j < NJ; j++)
                    mma16816(acc[i][j], af[i], bf[j]);
        }
        // no trailing barrier: top barrier of iteration t+1 provides the
        // write-after-read ordering for stage reuse (see header comment).
    }

    // ---- epilogue
    const float* pe_row = e.pe ? (e.pe + (size_t)(bm >> 9) * N) : (const float*)0;
    float* Cf = (float*)Cv;
    __half* Ch = (__half*)Cv;

    #pragma unroll
    for (int i = 0; i < MI; i++) {
        const int r0 = bm + warpm * (MI * 16) + i * 16 + fr;
        #pragma unroll
        for (int j = 0; j < NJ; j++) {
            const int c0 = bn + warpn * (NW * 32) + j * 8 + 2 * fc;
            float v[4];
            #pragma unroll
            for (int k = 0; k < 4; k++) {
                float x = acc[i][j][k];
                const int c = c0 + (k & 1);
                if (e.bias)  x += e.bias[c];
                if (e.bias2) x += e.bias2[c];
                if (pe_row)  x += pe_row[c];
                if (e.act)   x = eluf(x);
                if (e.bn_g)  x = (x - e.bn_m[c]) * e.bn_g[c] * rsqrtf(e.bn_v[c] + EPSF) + e.bn_b[c];
                v[k] = x;
            }
            if (HOUT) {
                *(__half2*)(Ch + (size_t)r0 * ldc + c0)       = __floats2half2_rn(v[0], v[1]);
                *(__half2*)(Ch + (size_t)(r0 + 8) * ldc + c0) = __floats2half2_rn(v[2], v[3]);
            } else {
                float* p0 = Cf + (size_t)r0 * ldc + c0;
                float* p1 = Cf + (size_t)(r0 + 8) * ldc + c0;
                if (e.accumulate) {
                    float2 o0 = *(float2*)p0, o1 = *(float2*)p1;
                    v[0] += o0.x; v[1] += o0.y; v[2] += o1.x; v[3] += o1.y;
                }
                *(float2*)p0 = make_float2(v[0], v[1]);
                *(float2*)p1 = make_float2(v[2], v[3]);
            }
        }
    }
}

// ---------------- fused preconversion kernels --------------------------------
// preconv1 (main stream): only KV-gemm data deps = pch + Wkv
#define P1_N1 ((size_t)Wwin * Bsz * Hdim / 4)
#define P1_N2 (P1_N1 + (size_t)NKV * Hdim / 4)

__global__ void preconv1(const float* __restrict__ pcells,
                         const float* __restrict__ Wk, const float* __restrict__ Wv)
{
    size_t i = (size_t)blockIdx.x * blockDim.x + threadIdx.x;
    if (i < P1_N1) {
        float4 v = ((const float4*)pcells)[i];
        cvt_store(g_pch + 4 * i, v);
    } else if (i < P1_N2) {
        size_t j = i - P1_N1;
        int n = (int)(j >> 8);
        int c = (int)(j & 255) * 4;
        const float* src = (n < Hdim) ? (Wk + (size_t)n * (Hdim + Pdim) + c)
                                      : (Wv + (size_t)(n - Hdim) * (Hdim + Pdim) + c);
        cvt_store(g_Wkvh + (size_t)n * Hdim + c, *(const float4*)src);
    }
}

// preconv2 (side stream): xh2, Wq, Wqa, Wo, Wpre
#define P2_N0 ((size_t)Bsz * KQ / 4)
#define P2_N1 (P2_N0 + (size_t)Hdim * KQ / 4)
#define P2_N2 (P2_N1 + (size_t)Hdim * Hdim / 4)
#define P2_N3 (P2_N2 + (size_t)Hdim * Hdim / 4)
#define P2_N4 (P2_N3 + (size_t)H4 * KPRE / 4)

__global__ void preconv2(const float* __restrict__ x, const float* __restrict__ ph,
                         const float* __restrict__ Wq, const float* __restrict__ Wqa,
                         const float* __restrict__ Wo,
                         const float* __restrict__ Wih, const float* __restrict__ Whh,
                         const float* __restrict__ Wac)
{
    size_t i = (size_t)blockIdx.x * blockDim.x + threadIdx.x;
    if (i < P2_N0) {
        int row = (int)(i / 384);
        int c = (int)(i - (size_t)row * 384) * 4;
        float4 v = (c < 512) ? *(const float4*)(x + (size_t)row * 512 + c)
                             : *(const float4*)(ph + (size_t)row * 1024 + (c - 512));
        cvt_store(g_xh2h + (size_t)row * KPRE + c, v);
    } else if (i < P2_N1) {
        size_t j = i - P2_N0;
        cvt_store(g_Wqh + 4 * j, ((const float4*)Wq)[j]);
    } else if (i < P2_N2) {
        size_t j = i - P2_N1;
        cvt_store(g_Wqah + 4 * j, ((const float4*)Wqa)[j]);
    } else if (i < P2_N3) {
        size_t j = i - P2_N2;
        cvt_store(g_Woh + 4 * j, ((const float4*)Wo)[j]);
    } else if (i < P2_N4) {
        size_t j = i - P2_N3;
        int row = (int)(j / 640);
        int c = (int)(j - (size_t)row * 640) * 4;
        const float* src;
        if (c < 512)       src = Wih + (size_t)row * 512 + c;
        else if (c < 1536) src = Whh + (size_t)row * 1024 + (c - 512);
        else               src = Wac + (size_t)row * 1024 + (c - 1536);
        cvt_store(g_Wpreh + (size_t)row * KPRE + c, *(const float4*)src);
    }
}

__global__ void pe_proj_kernel(const float* __restrict__ Wk, const float* __restrict__ bk,
                               const float* __restrict__ Wv, const float* __restrict__ bv)
{
    int w = blockIdx.x;
    int h = blockIdx.y * blockDim.x + threadIdx.x;
    const float* wkr = Wk + (size_t)h * (Hdim + Pdim) + Hdim;
    const float* wvr = Wv + (size_t)h * (Hdim + Pdim) + Hdim;
    float ak = bk[h], av = bv[h];
    const float c0 = logf(10000.0f) / (float)Pdim;
    #pragma unroll
    for (int i = 0; i < Pdim / 2; i++) {
        float div = expf(-(2.0f * i) * c0);
        float ang = (float)w * div;
        float s = sinf(ang), cc = cosf(ang);
        ak += s * wkr[2 * i] + cc * wkr[2 * i + 1];
        av += s * wvr[2 * i] + cc * wvr[2 * i + 1];
    }
    g_pekv[w * NKV + h]        = ak;
    g_pekv[w * NKV + Hdim + h] = av;
}

// ---------------- attention (vectorized loads) --------------------------------
__global__ __launch_bounds__(1024)
void attention_kernel()
{
    int b   = blockIdx.x;
    int tid = threadIdx.x;
    int warp = tid >> 5, lane = tid & 31;

    __shared__ float qs[Hdim];
    __shared__ float S [HEADS][Wwin];
    __shared__ float ps[HEADS][Wwin];

    qs[tid] = g_Q[(size_t)b * Hdim + tid];
    __syncthreads();

    // ---- scores: warp w handles window position w; uint4 (8-half) chunks.
    {
        const uint4* K4 = (const uint4*)(g_KV + ((size_t)warp * Bsz + b) * NKV);
        const float4* q4 = (const float4*)qs;
        float acc[4];
        #pragma unroll
        for (int j = 0; j < 4; j++) {
            const int o = lane * 8 + 256 * j;
            uint4 kv = K4[o >> 3];
            float4 qa = q4[o >> 2];
            float4 qb = q4[(o >> 2) + 1];
            const __half2* h2 = (const __half2*)&kv;
            float2 k0 = __half22float2(h2[0]);
            float2 k1 = __half22float2(h2[1]);
            float2 k2 = __half22float2(h2[2]);
            float2 k3 = __half22float2(h2[3]);
            float a = k0.x * qa.x + k0.y * qa.y + k1.x * qa.z + k1.y * qa.w;
            a += k2.x * qb.x + k2.y * qb.y + k3.x * qb.z + k3.y * qb.w;
            acc[j] = a;
        }
        #pragma unroll
        for (int j = 0; j < 4; j++) {
            #pragma unroll
            for (int off = 4; off; off >>= 1)
                acc[j] += __shfl_xor_sync(0xffffffffu, acc[j], off);
        }
        if ((lane & 7) == 0) {
            int g = lane >> 3;
            #pragma unroll
            for (int j = 0; j < 4; j++)
                S[g + 4 * j][warp] = acc[j] * 0.125f;   // 1/sqrt(64)
        }
    }
    __syncthreads();

    // ---- softmax: warp h over 32 positions
    if (warp < HEADS) {
        float s = S[warp][lane];
        float m = s;
        #pragma unroll
        for (int off = 16; off; off >>= 1)
            m = fmaxf(m, __shfl_xor_sync(0xffffffffu, m, off));
        float ev = expf(s - m);
        float sum = ev;
        #pragma unroll
        for (int off = 16; off; off >>= 1)
            sum += __shfl_xor_sync(0xffffffffu, sum, off);
        ps[warp][lane] = ev / sum;
    }
    __syncthreads();

    // ---- ctx: threads 0..511, half2 per thread
    if (tid < 512) {
        int h = tid >> 5;
        const __half2* Vb2 = (const __half2*)(g_KV + (size_t)b * NKV + Hdim) + tid;
        const size_t stride2 = (size_t)Bsz * NKV / 2;
        float ax = 0.f, ay = 0.f;
        #pragma unroll
        for (int w = 0; w < Wwin; w++) {
            float p = ps[h][w];
            float2 vf = __half22float2(Vb2[(size_t)w * stride2]);
            ax = fmaf(p, vf.x, ax);
            ay = fmaf(p, vf.y, ay);
        }
        ((__half2*)(g_ctxh + (size_t)b * Hdim))[tid] = __floats2half2_rn(ax, ay);
    }
}

__global__ void final_kernel(const float* __restrict__ pcell,
                             const float* __restrict__ gmm, const float* __restrict__ bb,
                             const float* __restrict__ mm, const float* __restrict__ vv,
                             float* __restrict__ out)
{
    int idx = blockIdx.x * blockDim.x + threadIdx.x;
    int r = idx >> 10, c = idx & 1023;
    const float* p = g_pre + (size_t)r * H4;
    float iv = tanhf(p[c]);
    float f  = 1.f / (1.f + expf(-p[1024 + c]));
    float ig = 1.f / (1.f + expf(-p[2048 + c]));
    float o  = 1.f / (1.f + expf(-p[3072 + c]));
    float cell = iv * ig + pcell[idx] * f;
    float e = eluf(cell);
    out[idx] = (o * e - mm[c]) * gmm[c] * rsqrtf(vv[c] + EPSF) + bb[c];
}

// ---------------- host --------------------------------------------------------
#define SMEM_S(TBM, TBN, KB) ((TBM + TBN) * (KB + 8) * 3 * 2)
#define SMEM_SM  SMEM_S(64, 64, 128)    // 104448
#define SMEM_MD  SMEM_S(64, 128, 64)    // 82944
#define SMEM_KV  SMEM_S(128, 128, 64)   // 110592

extern "C" void kernel_launch(void* const* d_in, const int* in_sizes, int n_in,
                              void* d_out, int out_size)
{
    const float* x      = (const float*)d_in[0];
    const float* ph     = (const float*)d_in[1];
    const float* pc     = (const float*)d_in[2];
    const float* pcells = (const float*)d_in[3];
    const float* W_ih   = (const float*)d_in[4];
    const float* b_ih   = (const float*)d_in[5];
    const float* W_hh   = (const float*)d_in[6];
    const float* W_q    = (const float*)d_in[7];
    const float* b_q    = (const float*)d_in[8];
    const float* W_ac   = (const float*)d_in[9];
    const float* b_ac   = (const float*)d_in[10];
    const float* Wq_a   = (const float*)d_in[11];
    const float* bq_a   = (const float*)d_in[12];
    const float* Wk_a   = (const float*)d_in[13];
    const float* bk_a   = (const float*)d_in[14];
    const float* Wv_a   = (const float*)d_in[15];
    const float* bv_a   = (const float*)d_in[16];
    const float* Wo_a   = (const float*)d_in[17];
    const float* bo_a   = (const float*)d_in[18];
    const float* bnag   = (const float*)d_in[19];
    const float* bnab   = (const float*)d_in[20];
    const float* bnam   = (const float*)d_in[21];
    const float* bnav   = (const float*)d_in[22];
    const float* bnpg   = (const float*)d_in[23];
    const float* bnpb   = (const float*)d_in[24];
    const float* bnpm   = (const float*)d_in[25];
    const float* bnpv   = (const float*)d_in[26];
    float* out = (float*)d_out;

    cudaFuncSetAttribute((const void*)hgemm<1,4,2,1,128,0>, cudaFuncAttributeMaxDynamicSharedMemorySize, SMEM_SM);
    cudaFuncSetAttribute((const void*)hgemm<1,4,2,1,128,1>, cudaFuncAttributeMaxDynamicSharedMemorySize, SMEM_SM);
    cudaFuncSetAttribute((const void*)hgemm<2,2,4,1,64,0>,  cudaFuncAttributeMaxDynamicSharedMemorySize, SMEM_MD);
    cudaFuncSetAttribute((const void*)hgemm<4,2,4,1,64,1>,  cudaFuncAttributeMaxDynamicSharedMemorySize, SMEM_KV);

    __half *pxh2, *pqh, *pKV, *pctxh, *pattnh, *ppch, *pWqh, *pWqah, *pWkvh, *pWoh, *pWpreh;
    float *pQ, *ppekv, *ppre;
    cudaGetSymbolAddress((void**)&pxh2,  g_xh2h);
    cudaGetSymbolAddress((void**)&pqh,   g_qh);
    cudaGetSymbolAddress((void**)&pQ,    g_Q);
    cudaGetSymbolAddress((void**)&ppekv, g_pekv);
    cudaGetSymbolAddress((void**)&pKV,   g_KV);
    cudaGetSymbolAddress((void**)&pctxh, g_ctxh);
    cudaGetSymbolAddress((void**)&pattnh,g_attnh);
    cudaGetSymbolAddress((void**)&ppre,  g_pre);
    cudaGetSymbolAddress((void**)&ppch,  g_pch);
    cudaGetSymbolAddress((void**)&pWqh,  g_Wqh);
    cudaGetSymbolAddress((void**)&pWqah, g_Wqah);
    cudaGetSymbolAddress((void**)&pWkvh, g_Wkvh);
    cudaGetSymbolAddress((void**)&pWoh,  g_Woh);
    cudaGetSymbolAddress((void**)&pWpreh,g_Wpreh);

    cudaStream_t s1;
    cudaEvent_t evF, evPE, evQ, evP;
    cudaStreamCreateWithFlags(&s1, cudaStreamNonBlocking);
    cudaEventCreateWithFlags(&evF,  cudaEventDisableTiming);
    cudaEventCreateWithFlags(&evPE, cudaEventDisableTiming);
    cudaEventCreateWithFlags(&evQ,  cudaEventDisableTiming);
    cudaEventCreateWithFlags(&evP,  cudaEventDisableTiming);

    Epi e0 = {};

    // fork side stream immediately
    cudaEventRecord(evF, 0);
    cudaStreamWaitEvent(s1, evF, 0);

    // ---- side stream: pe bias (tiny, off critical path), then conversions + q-chain
    pe_proj_kernel<<<dim3(Wwin, Hdim / 128), 128, 0, s1>>>(Wk_a, bk_a, Wv_a, bv_a);
    cudaEventRecord(evPE, s1);

    { int nb = (int)((P2_N4 + 255) / 256);
      preconv2<<<nb, 256, 0, s1>>>(x, ph, W_q, Wq_a, Wo_a, W_ih, W_hh, W_ac); }

    { Epi e = e0; e.bias = b_q; e.act = 1;
      hgemm<1,4,2,1,128,1><<<dim3(Hdim/64, Bsz/64), 256, SMEM_SM, s1>>>(
          pxh2, pWqh, pqh, Bsz, Hdim, KQ, KPRE, KQ, Hdim, e); }

    { Epi e = e0; e.bias = bq_a;
      hgemm<1,4,2,1,128,0><<<dim3(Hdim/64, Bsz/64), 256, SMEM_SM, s1>>>(
          pqh, pWqah, pQ, Bsz, Hdim, Hdim, Hdim, Hdim, Hdim, e); }
    cudaEventRecord(evQ, s1);

    // ---- main stream: minimal KV deps, then KV
    { int nb = (int)((P1_N2 + 255) / 256);
      preconv1<<<nb, 256>>>(pcells, Wk_a, Wv_a); }

    // KV needs pe bias from the side stream (ready long before preconv1 ends)
    cudaStreamWaitEvent(0, evPE, 0);
    { Epi e = e0; e.pe = ppekv; e.act = 1;
      hgemm<4,2,4,1,64,1><<<dim3(NKV/128, (Wwin*Bsz)/128), 256, SMEM_KV>>>(
          ppch, pWkvh, pKV, Wwin*Bsz, NKV, Hdim, Hdim, Hdim, NKV, e); }

    // side: pre1 = [x|ph] @ W[:, :1536]^T + b_ih + b_ac (hidden under KV)
    { Epi e = e0; e.bias = b_ih; e.bias2 = b_ac;
      hgemm<2,2,4,1,64,0><<<dim3(H4/128, Bsz/64), 256, SMEM_MD, s1>>>(
          pxh2, pWpreh, ppre, Bsz, H4, KQ, KPRE, KPRE, H4, e); }
    cudaEventRecord(evP, s1);

    // join: attention needs Q (side) + KV (main)
    cudaStreamWaitEvent(0, evQ, 0);
    attention_kernel<<<Bsz, 1024>>>();

    // attn = BN(elu(ctx @ Wo_a^T + bo_a)) -> fp16
    { Epi e = e0; e.bias = bo_a; e.act = 1;
      e.bn_g = bnag; e.bn_b = bnab; e.bn_m = bnam; e.bn_v = bnav;
      hgemm<1,4,2,1,128,1><<<dim3(Hdim/64, Bsz/64), 256, SMEM_SM>>>(
          pctxh, pWoh, pattnh, Bsz, Hdim, Hdim, Hdim, Hdim, Hdim, e); }

    // pre2: pre += attn @ W_ac^T  (MD shape: 256 CTAs = sub-one-wave)
    cudaStreamWaitEvent(0, evP, 0);
    { Epi e = e0; e.accumulate = 1;
      hgemm<2,2,4,1,64,0><<<dim3(H4/128, Bsz/64), 256, SMEM_MD>>>(
          pattnh, pWpreh + KQ, ppre, Bsz, H4, Hdim, Hdim, KPRE, H4, e); }

    // LSTM tail + post-BN -> out
    final_kernel<<<(Bsz * Hdim) / 256, 256>>>(pc, bnpg, bnpb, bnpm, bnpv, out);
}